// round 13
// baseline (speedup 1.0000x reference)
#include <cuda_runtime.h>
#include <cuda_fp16.h>
#include <stdint.h>
#include <math.h>

#define B_   1024
#define T_   64
#define D_   512
#define HID_ 256
#define NH_  4
#define HD_  128
#define BT_  (B_*T_)

// ---------------- scratch ----------------
__device__ float  g_zstack[(size_t)BT_*D_];   // [B,T,D] trajectory (fp32)
__device__ float  g_zmean[B_*D_];             // mean over T
__device__ __half g_qkvh[(size_t)BT_*3*D_];   // qkv fp16
__device__ float  g_atto[(size_t)BT_*D_];     // att_out fp32
__device__ __half g_ctxh[(size_t)BT_*D_];     // attention context fp16
// packed fp16 fragment-major weights
__device__ __half g_W1p[HID_*D_];
__device__ __half g_W2p[HID_*HID_];
__device__ __half g_W3p[D_*HID_];
__device__ __half g_Wqkvf[3*D_*D_];
__device__ __half g_Wof[D_*D_];

// ---------------- helpers ----------------
// Fast erf (Abramowitz-Stegun 7.1.26, |abs err| <= 1.5e-7 — far below fp16 ulp)
__device__ __forceinline__ float erf_fast(float x) {
    float ax = fabsf(x);
    float t = __frcp_rn(1.0f + 0.3275911f * ax);
    float y = t * (0.254829592f + t * (-0.284496736f + t * (1.421413741f +
              t * (-1.453152027f + t * 1.061405429f))));
    float r = 1.0f - y * __expf(-ax * ax);
    return copysignf(r, x);
}

__device__ __forceinline__ float gelu_f(float x) {
    return 0.5f * x * (1.0f + erf_fast(x * 0.70710678118654752f));
}

__device__ __forceinline__ void mma16816(float* c, uint32_t a0, uint32_t a1,
                                         uint32_t a2, uint32_t a3,
                                         uint32_t b0, uint32_t b1) {
    asm volatile(
        "mma.sync.aligned.m16n8k16.row.col.f32.f16.f16.f32 "
        "{%0,%1,%2,%3}, {%4,%5,%6,%7}, {%8,%9}, {%0,%1,%2,%3};\n"
        : "+f"(c[0]), "+f"(c[1]), "+f"(c[2]), "+f"(c[3])
        : "r"(a0), "r"(a1), "r"(a2), "r"(a3), "r"(b0), "r"(b1));
}

__device__ __forceinline__ void ldsm_x4(uint32_t& a0, uint32_t& a1, uint32_t& a2,
                                        uint32_t& a3, uint32_t saddr) {
    asm volatile("ldmatrix.sync.aligned.m8n8.x4.shared.b16 {%0,%1,%2,%3}, [%4];\n"
                 : "=r"(a0), "=r"(a1), "=r"(a2), "=r"(a3) : "r"(saddr));
}

__device__ __forceinline__ void ldsm_x2(uint32_t& b0, uint32_t& b1, uint32_t saddr) {
    asm volatile("ldmatrix.sync.aligned.m8n8.x2.shared.b16 {%0,%1}, [%2];\n"
                 : "=r"(b0), "=r"(b1) : "r"(saddr));
}

__device__ __forceinline__ void ldsm_x2t(uint32_t& b0, uint32_t& b1, uint32_t saddr) {
    asm volatile("ldmatrix.sync.aligned.m8n8.x2.trans.shared.b16 {%0,%1}, [%2];\n"
                 : "=r"(b0), "=r"(b1) : "r"(saddr));
}

__device__ __forceinline__ uint32_t smem_u32(const void* p) {
    uint32_t a;
    asm("{ .reg .u64 t; cvta.to.shared.u64 t, %1; cvt.u32.u64 %0, t; }"
        : "=r"(a) : "l"(p));
    return a;
}

// L2-only (no L1 allocation) vector load
__device__ __forceinline__ uint4 ldcg4(const uint4* p) {
    return __ldcg(p);
}

// ---------------- weight packing (A-operand fragment-major, for ODE) ----------------
__global__ void pack_w(const float* __restrict__ W, __half* __restrict__ out, int nM, int K) {
    int idx = blockIdx.x * 256 + threadIdx.x;
    int j    = idx & 7;
    int lane = (idx >> 3) & 31;
    int tile = idx >> 8;
    int mt = tile % nM;
    int ks = tile / nM;
    int gid = lane >> 2, tig = lane & 3;
    int rr = gid + ((j >> 1) & 1) * 8;
    int cc = tig * 2 + (j & 1) + ((j >> 2) & 1) * 8;
    out[idx] = __float2half_rn(W[(size_t)(mt * 16 + rr) * K + ks * 16 + cc]);
}

// ---------------- weight packing (B-operand fragment-major, for hgemm) ----------------
__device__ __forceinline__ void pack_wb_one(const float* W, __half* out, int idx, int N, int K) {
    int h    = idx & 3;
    int lane = (idx >> 2) & 31;
    int rest = idx >> 7;
    int NKS = K / 16;
    int ks = rest % NKS;
    int nt = rest / NKS;
    int n = nt * 8 + (lane >> 2);
    int k = ks * 16 + (lane & 3) * 2 + (h & 1) + ((h >> 1) << 3);
    out[idx] = __float2half_rn(W[(size_t)n * K + k]);
}

__global__ void pack_wb2(const float* __restrict__ Wqkv, const float* __restrict__ Wo) {
    int idx = blockIdx.x * 256 + threadIdx.x;
    if (idx < 3 * D_ * D_) {
        pack_wb_one(Wqkv, g_Wqkvf, idx, 3 * D_, D_);
    } else {
        pack_wb_one(Wo, g_Wof, idx - 3 * D_ * D_, D_, D_);
    }
}

// ---------------- fused persistent ODE kernel (MB=8, 128 CTAs, 512 threads) ----------------
#define MB  8
#define ZP  516
#define ZBP 520
#define HP  264
#define SMEM_ODE (2*MB*ZP*4 + MB*ZBP*2 + 2*MB*HP*2)   // 49792

template<int NM, int NK, bool GELU, bool CG>
__device__ __forceinline__ void gemm_act(
    const __half* __restrict__ Wp, const float* __restrict__ bias,
    const __half* __restrict__ act, int ap,
    __half* __restrict__ out, int op, int warp, int lane)
{
    int gid = lane >> 2, tig = lane & 3;
    #pragma unroll
    for (int mt = warp; mt < NM; mt += 16) {
        float c0[4] = {0.f,0.f,0.f,0.f};
        const uint4* wp = (const uint4*)Wp + mt * 32 + lane;
        const __half* a0p = act + gid * ap + tig * 2;
        #pragma unroll 8
        for (int ks = 0; ks < NK; ks++) {
            uint4 a = CG ? ldcg4(wp + (size_t)ks * NM * 32)
                         : wp[(size_t)ks * NM * 32];
            uint32_t b00 = *(const uint32_t*)(a0p + ks * 16);
            uint32_t b01 = *(const uint32_t*)(a0p + ks * 16 + 8);
            mma16816(c0, a.x, a.y, a.z, a.w, b00, b01);
        }
        int h0 = mt * 16 + gid;
        float bs0 = __ldg(bias + h0);
        float bs1 = __ldg(bias + h0 + 8);
        int r = tig * 2;
        float v;
        v = c0[0] + bs0; if (GELU) v = gelu_f(v); out[(r + 0) * op + h0    ] = __float2half_rn(v);
        v = c0[1] + bs0; if (GELU) v = gelu_f(v); out[(r + 1) * op + h0    ] = __float2half_rn(v);
        v = c0[2] + bs1; if (GELU) v = gelu_f(v); out[(r + 0) * op + h0 + 8] = __float2half_rn(v);
        v = c0[3] + bs1; if (GELU) v = gelu_f(v); out[(r + 1) * op + h0 + 8] = __float2half_rn(v);
    }
}

// gemm3: RK4 stage update. FINAL=false: Zacc += w*k, stage Zbf = h(Z + c*k).
// FINAL=true (e==3): z = Zacc + w*k (nan->0); write Z/Zacc/Zbf/zstack; zsum += z.
template<bool FINAL>
__device__ __forceinline__ void gemm3_stage(
    const __half* __restrict__ Wp, const float* __restrict__ b3,
    const __half* __restrict__ act,
    float* Z, float* Zacc, __half* Zbf,
    float wcoef, float ccoef, float* zsum,
    float* __restrict__ gstack,            // g_zstack + (r0*T + t)*D (FINAL only)
    int warp, int lane)
{
    constexpr int NM = 32, NK = 16;
    int gid = lane >> 2, tig = lane & 3;
    float c0[4] = {0.f,0.f,0.f,0.f}, c1[4] = {0.f,0.f,0.f,0.f};
    const uint4* wp0 = (const uint4*)Wp + warp * 32 + lane;
    const uint4* wp1 = wp0 + 16 * 32;
    const __half* a0p = act + gid * HP + tig * 2;
    #pragma unroll 8
    for (int ks = 0; ks < NK; ks++) {
        uint4 a0 = ldcg4(wp0 + (size_t)ks * NM * 32);
        uint4 a1 = ldcg4(wp1 + (size_t)ks * NM * 32);
        uint32_t b00 = *(const uint32_t*)(a0p + ks * 16);
        uint32_t b01 = *(const uint32_t*)(a0p + ks * 16 + 8);
        mma16816(c0, a0.x, a0.y, a0.z, a0.w, b00, b01);
        mma16816(c1, a1.x, a1.y, a1.z, a1.w, b00, b01);
    }
    int idx8 = 0;
    #pragma unroll
    for (int m = 0; m < 2; m++) {
        const float* cm = m ? c1 : c0;
        int d0 = (warp + m * 16) * 16 + gid;
        float bv0 = __ldg(b3 + d0);
        float bv1 = __ldg(b3 + d0 + 8);
        int r = tig * 2;
        float k;
        #define ODE_DO(cc_, dd_, rr_, bb_)                                          \
            { k = (cc_) + (bb_);                                                    \
              if (FINAL) {                                                          \
                  float z = Zacc[(rr_) * ZP + (dd_)] + wcoef * k;                   \
                  if (isnan(z)) z = 0.f;                                            \
                  Zacc[(rr_) * ZP + (dd_)] = z;                                     \
                  Z[(rr_) * ZP + (dd_)] = z;                                        \
                  Zbf[(rr_) * ZBP + (dd_)] = __float2half_rn(z);                    \
                  zsum[idx8] += z;                                                  \
                  gstack[(size_t)(rr_) * (T_ * D_) + (dd_)] = z;                    \
              } else {                                                              \
                  Zacc[(rr_) * ZP + (dd_)] += wcoef * k;                            \
                  Zbf[(rr_) * ZBP + (dd_)] =                                        \
                      __float2half_rn(Z[(rr_) * ZP + (dd_)] + ccoef * k);           \
              }                                                                     \
              idx8++; }
        ODE_DO(cm[0], d0,     r,     bv0)
        ODE_DO(cm[1], d0,     r + 1, bv0)
        ODE_DO(cm[2], d0 + 8, r,     bv1)
        ODE_DO(cm[3], d0 + 8, r + 1, bv1)
        #undef ODE_DO
    }
}

__global__ void __launch_bounds__(512, 1) ode_kernel(
    const float* __restrict__ zinit, const float* __restrict__ tsteps,
    const float* __restrict__ b1, const float* __restrict__ b2,
    const float* __restrict__ b3)
{
    extern __shared__ char smchar[];
    float*  Z    = (float*)(smchar);
    float*  Zacc = (float*)(smchar + MB * ZP * 4);
    __half* Zbf  = (__half*)(smchar + 2 * MB * ZP * 4);
    __half* H1   = (__half*)(smchar + 2 * MB * ZP * 4 + MB * ZBP * 2);
    __half* H2   = H1 + MB * HP;

    int tid = threadIdx.x, warp = tid >> 5, lane = tid & 31;
    int r0 = blockIdx.x * MB;
    float dt = __ldg(tsteps + 1) - __ldg(tsteps);

    // ---- input-adaptive scale (one warp per row, warps 0-7) ----
    if (warp < MB) {
        int r = warp;
        int sub = lane;
        const float* zr = zinit + (size_t)(r0 + r) * D_;
        float vals[16];
        float s = 0.f, ss = 0.f;
        #pragma unroll
        for (int i = 0; i < 16; i++) {
            float v = zr[sub + i * 32];
            vals[i] = v; s += v; ss += v * v;
        }
        for (int o = 16; o; o >>= 1) {
            s  += __shfl_down_sync(0xffffffffu, s,  o);
            ss += __shfl_down_sync(0xffffffffu, ss, o);
        }
        s  = __shfl_sync(0xffffffffu, s,  0);
        ss = __shfl_sync(0xffffffffu, ss, 0);
        float mean = s * (1.f / D_);
        float var  = (ss - s * mean) * (1.f / (D_ - 1));
        float sc   = sqrtf(ss) / (var + 1e-6f);
        sc = fminf(fmaxf(sc, 0.8f), 1.2f);
        #pragma unroll
        for (int i = 0; i < 16; i++) {
            float z = vals[i] * sc;
            int d = sub + i * 32;
            Z[r * ZP + d] = z;
            Zacc[r * ZP + d] = z;
            Zbf[r * ZBP + d] = __float2half_rn(z);
        }
    }
    __syncthreads();

    const float wc[4] = {1.f, 2.f, 2.f, 1.f};
    const float cc[4] = {0.5f, 0.5f, 1.f, 0.f};

    float zsum[8];
    #pragma unroll
    for (int j = 0; j < 8; j++) zsum[j] = 0.f;

    for (int t = 0; t < T_; t++) {
        #pragma unroll 1
        for (int e = 0; e < 3; e++) {
            gemm_act<16, 32, true, true >(g_W1p, b1, Zbf, ZBP, H1, HP, warp, lane);
            __syncthreads();
            gemm_act<16, 16, true, false>(g_W2p, b2, H1, HP, H2, HP, warp, lane);
            __syncthreads();
            gemm3_stage<false>(g_W3p, b3, H2, Z, Zacc, Zbf,
                               dt * (1.f / 6.f) * wc[e], dt * cc[e],
                               zsum, nullptr, warp, lane);
            __syncthreads();
        }
        // e == 3: fused finalize
        gemm_act<16, 32, true, true >(g_W1p, b1, Zbf, ZBP, H1, HP, warp, lane);
        __syncthreads();
        gemm_act<16, 16, true, false>(g_W2p, b2, H1, HP, H2, HP, warp, lane);
        __syncthreads();
        gemm3_stage<true>(g_W3p, b3, H2, Z, Zacc, Zbf,
                          dt * (1.f / 6.f), 0.f,
                          zsum, g_zstack + ((size_t)r0 * T_ + t) * D_, warp, lane);
        __syncthreads();
    }

    // ---- write zmean (gemm3 thread mapping; t-ascending sum order preserved) ----
    {
        int gid = lane >> 2, tig = lane & 3;
        int idx8 = 0;
        #pragma unroll
        for (int m = 0; m < 2; m++) {
            int d0 = (warp + m * 16) * 16 + gid;
            int r = tig * 2;
            g_zmean[(size_t)(r0 + r)     * D_ + d0    ] = zsum[idx8++] * (1.0f / T_);
            g_zmean[(size_t)(r0 + r + 1) * D_ + d0    ] = zsum[idx8++] * (1.0f / T_);
            g_zmean[(size_t)(r0 + r)     * D_ + d0 + 8] = zsum[idx8++] * (1.0f / T_);
            g_zmean[(size_t)(r0 + r + 1) * D_ + d0 + 8] = zsum[idx8++] * (1.0f / T_);
        }
    }
}

// ---------------- hgemm + optional fused z_dc A-prep ----------------
#define AP 520
#define SMEM_HG (128*AP*2)

template<int NTOT, int MODE, typename OT>
__global__ void __launch_bounds__(256, 1) hgemm(
    const __half* __restrict__ Act,
    const float* __restrict__ zstack, const float* __restrict__ zmean,
    const float* __restrict__ zinit,
    const __half* __restrict__ Wf,
    const float* __restrict__ bias, OT* __restrict__ C)
{
    extern __shared__ __half As[];
    int tid = threadIdx.x, warp = tid >> 5, lane = tid & 31;
    int m0 = blockIdx.x * 128;

    if (MODE == 0) {
        for (int i = tid; i < 128 * 64; i += 256) {
            int r = i >> 6, c = i & 63;
            *(uint4*)&As[r * AP + c * 8] =
                *(const uint4*)&Act[(size_t)(m0 + r) * 512 + c * 8];
        }
    } else {
        for (int i = tid; i < 128 * 128; i += 256) {
            int r = i >> 7, c = (i & 127) * 4;
            int row = m0 + r;
            int b = row >> 6;
            float4 zs = *(const float4*)&zstack[(size_t)row * 512 + c];
            float4 zm = *(const float4*)&zmean[(size_t)b * 512 + c];
            float4 zi = *(const float4*)&zinit[(size_t)b * 512 + c];
            __half2 h01 = __floats2half2_rn(zs.x - 0.05f * (zm.x - zi.x),
                                            zs.y - 0.05f * (zm.y - zi.y));
            __half2 h23 = __floats2half2_rn(zs.z - 0.05f * (zm.z - zi.z),
                                            zs.w - 0.05f * (zm.w - zi.w));
            uint2 u;
            u.x = *(uint32_t*)&h01; u.y = *(uint32_t*)&h23;
            *(uint2*)&As[r * AP + c] = u;
        }
    }
    __syncthreads();

    int mw = warp * 16;
    int arow = mw + (lane & 7) + ((lane >> 3) & 1) * 8;
    int acol = ((lane >> 4) & 1) * 8;
    uint32_t abase = smem_u32(As) + (arow * AP + acol) * 2;

    int r = lane >> 2, cpair = (lane & 3) * 2;

    for (int ng = 0; ng < NTOT / 64; ng++) {
        float acc[8][4];
        #pragma unroll
        for (int j = 0; j < 8; j++)
            #pragma unroll
            for (int q = 0; q < 4; q++) acc[j][q] = 0.f;

        const uint2* wbase = (const uint2*)Wf + ((size_t)ng * 8 * 32) * 32 + lane;
        #pragma unroll 4
        for (int ks = 0; ks < 32; ks++) {
            uint32_t a0, a1, a2, a3;
            ldsm_x4(a0, a1, a2, a3, abase + ks * 32);
            #pragma unroll
            for (int j = 0; j < 8; j++) {
                uint2 b = wbase[((size_t)j * 32 + ks) * 32];
                mma16816(acc[j], a0, a1, a2, a3, b.x, b.y);
            }
        }
        #pragma unroll
        for (int j = 0; j < 8; j++) {
            int n = ng * 64 + j * 8 + cpair;
            float bv0 = __ldg(bias + n), bv1 = __ldg(bias + n + 1);
            float v00 = acc[j][0] + bv0, v01 = acc[j][1] + bv1;
            float v10 = acc[j][2] + bv0, v11 = acc[j][3] + bv1;
            if (sizeof(OT) == 2) {
                __half2 lo = __floats2half2_rn(v00, v01);
                __half2 hi = __floats2half2_rn(v10, v11);
                *(uint32_t*)&C[(size_t)(m0 + mw + r)     * NTOT + n] = *(uint32_t*)&lo;
                *(uint32_t*)&C[(size_t)(m0 + mw + r + 8) * NTOT + n] = *(uint32_t*)&hi;
            } else {
                *(float2*)&C[(size_t)(m0 + mw + r)     * NTOT + n] = make_float2(v00, v01);
                *(float2*)&C[(size_t)(m0 + mw + r + 8) * NTOT + n] = make_float2(v10, v11);
            }
        }
    }
}

// ---------------- tensor-core attention: per (b,h), 128 threads ----------------
#define VP 136                               // Q/K/V fp16 pitch
#define PP 72                                // P fp16 pitch
#define AT_QS 0
#define AT_KS (64*VP*2)                      // 17408
#define AT_VS (2*64*VP*2)                    // 34816
#define AT_S  (3*64*VP*2)                    // 52224 (fp32, pitch 65)
#define AT_PS (AT_S + 64*65*4)               // 68864
#define ATTN_SMEM_BYTES (AT_PS + 64*PP*2)    // 78080

__global__ void __launch_bounds__(128, 1) attn_kernel() {
    extern __shared__ char sm[];
    __half* Qs = (__half*)(sm + AT_QS);
    __half* Ks = (__half*)(sm + AT_KS);
    __half* Vs = (__half*)(sm + AT_VS);
    float*  S  = (float*)(sm + AT_S);
    __half* Ps = (__half*)(sm + AT_PS);

    int tid = threadIdx.x, warp = tid >> 5, lane = tid & 31;
    int bh = blockIdx.x;
    int b = bh >> 2, h = bh & 3;
    int gid = lane >> 2, tig = lane & 3;

    // ---- load Q,K,V fp16 directly ----
    for (int idx = tid; idx < 64 * 16; idx += 128) {
        int t = idx >> 4, c = (idx & 15) * 8;
        size_t base = ((size_t)(b * T_ + t)) * (3 * D_) + h * HD_ + c;
        #pragma unroll
        for (int w = 0; w < 3; w++) {
            *(uint4*)&((__half*)(sm + w * 64 * VP * 2))[t * VP + c] =
                *(const uint4*)&g_qkvh[base + (size_t)w * D_];
        }
    }
    __syncthreads();

    // ---- scores: warp computes rows [warp*16, warp*16+16) x 64 ----
    int m0 = warp * 16;
    {
        uint32_t qbase = smem_u32(Qs) +
            ((m0 + (lane & 7) + ((lane >> 3) & 1) * 8) * VP + ((lane >> 4) & 1) * 8) * 2;
        uint32_t kbase = smem_u32(Ks) +
            (((lane & 15) & 7) * VP + (((lane & 15) >> 3)) * 8) * 2;
        float c[8][4];
        #pragma unroll
        for (int j = 0; j < 8; j++)
            #pragma unroll
            for (int q = 0; q < 4; q++) c[j][q] = 0.f;
        #pragma unroll
        for (int ks = 0; ks < 8; ks++) {
            uint32_t a0, a1, a2, a3;
            ldsm_x4(a0, a1, a2, a3, qbase + ks * 32);
            #pragma unroll
            for (int j = 0; j < 8; j++) {
                uint32_t b0, b1;
                ldsm_x2(b0, b1, kbase + (j * 8 * VP + ks * 16) * 2);
                mma16816(c[j], a0, a1, a2, a3, b0, b1);
            }
        }
        const float sc = 0.08838834764831845f;   // 1/sqrt(128)
        #pragma unroll
        for (int j = 0; j < 8; j++) {
            int col = j * 8 + tig * 2;
            S[(m0 + gid)     * 65 + col]     = c[j][0] * sc;
            S[(m0 + gid)     * 65 + col + 1] = c[j][1] * sc;
            S[(m0 + gid + 8) * 65 + col]     = c[j][2] * sc;
            S[(m0 + gid + 8) * 65 + col + 1] = c[j][3] * sc;
        }
    }
    __syncthreads();

    // ---- softmax: 2 threads per row ----
    {
        int r = tid >> 1, hf = tid & 1;
        float* Srow = S + r * 65 + hf * 32;
        float lmax = -1e30f;
        #pragma unroll
        for (int j = 0; j < 32; j++) lmax = fmaxf(lmax, Srow[j]);
        lmax = fmaxf(lmax, __shfl_xor_sync(0xffffffffu, lmax, 1));
        float lsum = 0.f;
        #pragma unroll
        for (int j = 0; j < 32; j++) {
            float e = expf(Srow[j] - lmax);
            Srow[j] = e;
            lsum += e;
        }
        lsum += __shfl_xor_sync(0xffffffffu, lsum, 1);
        float inv = 1.0f / lsum;
        __half* Prow = Ps + r * PP + hf * 32;
        #pragma unroll
        for (int j = 0; j < 16; j++) {
            __half2 p = __floats2half2_rn(Srow[j * 2] * inv, Srow[j * 2 + 1] * inv);
            *(uint32_t*)&Prow[j * 2] = *(uint32_t*)&p;
        }
    }
    __syncthreads();

    // ---- ctx = P @ V : warp computes rows m0..m0+15 x 128, two 64-col halves ----
    {
        uint32_t pbase = smem_u32(Ps) +
            ((m0 + (lane & 7) + ((lane >> 3) & 1) * 8) * PP + ((lane >> 4) & 1) * 8) * 2;
        uint32_t vbase = smem_u32(Vs) + ((lane & 15) * VP) * 2;
        #pragma unroll
        for (int dh = 0; dh < 2; dh++) {
            float c[8][4];
            #pragma unroll
            for (int j = 0; j < 8; j++)
                #pragma unroll
                for (int q = 0; q < 4; q++) c[j][q] = 0.f;
            #pragma unroll
            for (int ks = 0; ks < 4; ks++) {
                uint32_t a0, a1, a2, a3;
                ldsm_x4(a0, a1, a2, a3, pbase + ks * 32);
                #pragma unroll
                for (int j = 0; j < 8; j++) {
                    int d0 = dh * 64 + j * 8;
                    uint32_t b0, b1;
                    ldsm_x2t(b0, b1, vbase + (ks * 16 * VP + d0) * 2);
                    mma16816(c[j], a0, a1, a2, a3, b0, b1);
                }
            }
            #pragma unroll
            for (int j = 0; j < 8; j++) {
                int d0 = dh * 64 + j * 8 + tig * 2;
                size_t base0 = ((size_t)(b * T_ + m0 + gid))     * D_ + h * HD_ + d0;
                size_t base1 = ((size_t)(b * T_ + m0 + gid + 8)) * D_ + h * HD_ + d0;
                __half2 lo = __floats2half2_rn(c[j][0], c[j][1]);
                __half2 hi = __floats2half2_rn(c[j][2], c[j][3]);
                *(uint32_t*)&g_ctxh[base0] = *(uint32_t*)&lo;
                *(uint32_t*)&g_ctxh[base1] = *(uint32_t*)&hi;
            }
        }
    }
}

// ---------------- residual + LayerNorm ----------------
__global__ void ln_kernel(const float* __restrict__ zinit, const float* __restrict__ gamma,
                          const float* __restrict__ beta, float* __restrict__ out) {
    int row = blockIdx.x;
    int b = row >> 6;
    int tid = threadIdx.x;
    const float* ao = g_atto;
    float x[4];
    float s = 0.f, ss = 0.f;
    #pragma unroll
    for (int q = 0; q < 4; q++) {
        int d = tid + q * 128;
        float zs  = g_zstack[(size_t)row * D_ + d];
        float zdc = zs - 0.05f * (g_zmean[(size_t)b * D_ + d] - zinit[(size_t)b * D_ + d]);
        float v = zdc + ao[(size_t)row * D_ + d];
        x[q] = v; s += v; ss += v * v;
    }
    __shared__ float rs[4], rss[4];
    for (int o = 16; o; o >>= 1) {
        s  += __shfl_down_sync(0xffffffffu, s,  o);
        ss += __shfl_down_sync(0xffffffffu, ss, o);
    }
    if ((tid & 31) == 0) { rs[tid >> 5] = s; rss[tid >> 5] = ss; }
    __syncthreads();
    float sum   = rs[0] + rs[1] + rs[2] + rs[3];
    float sumsq = rss[0] + rss[1] + rss[2] + rss[3];
    float mean = sum * (1.0f / D_);
    float var  = sumsq * (1.0f / D_) - mean * mean;
    float inv  = rsqrtf(var + 1e-5f);
    #pragma unroll
    for (int q = 0; q < 4; q++) {
        int d = tid + q * 128;
        float o = (x[q] - mean) * inv * gamma[d] + beta[d];
        if (isnan(o)) o = 0.f;
        out[(size_t)row * D_ + d] = o;
    }
}

// ---------------- host orchestration ----------------
extern "C" void kernel_launch(void* const* d_in, const int* in_sizes, int n_in,
                              void* d_out, int out_size)
{
    const float* z_init = (const float*)d_in[0];
    const float* tsteps = (const float*)d_in[1];
    const float* W1     = (const float*)d_in[2];
    const float* b1     = (const float*)d_in[3];
    const float* W2     = (const float*)d_in[4];
    const float* b2     = (const float*)d_in[5];
    const float* W3     = (const float*)d_in[6];
    const float* b3     = (const float*)d_in[7];
    const float* Wqkv   = (const float*)d_in[8];
    const float* bqkv   = (const float*)d_in[9];
    const float* Wo     = (const float*)d_in[10];
    const float* bo     = (const float*)d_in[11];
    const float* gamma  = (const float*)d_in[12];
    const float* beta   = (const float*)d_in[13];

    float *zstack, *zmean, *atto;
    __half *w1p, *w2p, *w3p, *wqkvf, *wof, *ctxh, *qkvh;
    cudaGetSymbolAddress((void**)&zstack, g_zstack);
    cudaGetSymbolAddress((void**)&zmean,  g_zmean);
    cudaGetSymbolAddress((void**)&atto,   g_atto);
    cudaGetSymbolAddress((void**)&qkvh,   g_qkvh);
    cudaGetSymbolAddress((void**)&w1p,    g_W1p);
    cudaGetSymbolAddress((void**)&w2p,    g_W2p);
    cudaGetSymbolAddress((void**)&w3p,    g_W3p);
    cudaGetSymbolAddress((void**)&wqkvf,  g_Wqkvf);
    cudaGetSymbolAddress((void**)&wof,    g_Wof);
    cudaGetSymbolAddress((void**)&ctxh,   g_ctxh);

    cudaFuncSetAttribute(attn_kernel, cudaFuncAttributeMaxDynamicSharedMemorySize,
                         ATTN_SMEM_BYTES);
    cudaFuncSetAttribute(ode_kernel, cudaFuncAttributeMaxDynamicSharedMemorySize,
                         SMEM_ODE);
    cudaFuncSetAttribute(hgemm<3*D_, 1, __half>, cudaFuncAttributeMaxDynamicSharedMemorySize,
                         SMEM_HG);
    cudaFuncSetAttribute(hgemm<D_, 0, float>, cudaFuncAttributeMaxDynamicSharedMemorySize,
                         SMEM_HG);

    // 0) pack weights
    pack_w<<<(HID_ * D_) / 256, 256>>>(W1, w1p, HID_ / 16, D_);
    pack_w<<<(HID_ * HID_) / 256, 256>>>(W2, w2p, HID_ / 16, HID_);
    pack_w<<<(D_ * HID_) / 256, 256>>>(W3, w3p, D_ / 16, HID_);
    pack_wb2<<<(4 * D_ * D_) / 256, 256>>>(Wqkv, Wo);

    // 1) fused scale + full RK4 trajectory + zmean (128 CTAs)
    ode_kernel<<<B_ / MB, 512, SMEM_ODE>>>(z_init, tsteps, b1, b2, b3);

    // 2) QKV projection (fused z_dc prep, fp16 output)
    hgemm<3*D_, 1, __half><<<BT_ / 128, 256, SMEM_HG>>>(
        nullptr, zstack, zmean, z_init, wqkvf, bqkv, qkvh);

    // 3) tensor-core attention per (b,h)
    attn_kernel<<<B_ * NH_, 128, ATTN_SMEM_BYTES>>>();

    // 4) output projection (att_out fp32)
    hgemm<D_, 0, float><<<BT_ / 128, 256, SMEM_HG>>>(
        ctxh, nullptr, nullptr, nullptr, wof, bo, atto);

    // 5) residual + LayerNorm
    ln_kernel<<<BT_, 128>>>(z_init, gamma, beta, (float*)d_out);
}

// round 14
// speedup vs baseline: 1.4122x; 1.4122x over previous
#include <cuda_runtime.h>
#include <cuda_fp16.h>
#include <stdint.h>
#include <math.h>

#define B_   1024
#define T_   64
#define D_   512
#define HID_ 256
#define NH_  4
#define HD_  128
#define BT_  (B_*T_)

// ---------------- scratch ----------------
__device__ float  g_zstack[(size_t)BT_*D_];   // [B,T,D] trajectory (fp32)
__device__ float  g_zmean[B_*D_];             // mean over T
__device__ __half g_qkvh[(size_t)BT_*3*D_];   // qkv fp16
__device__ float  g_atto[(size_t)BT_*D_];     // att_out fp32
__device__ __half g_ctxh[(size_t)BT_*D_];     // attention context fp16
// packed fp16 fragment-major weights
__device__ __half g_W1p[HID_*D_];
__device__ __half g_W2p[HID_*HID_];
__device__ __half g_W3p[D_*HID_];
__device__ __half g_Wqkvf[3*D_*D_];
__device__ __half g_Wof[D_*D_];

// ---------------- helpers ----------------
// Fast erf (Abramowitz-Stegun 7.1.26, |abs err| <= 1.5e-7 — far below fp16 ulp)
__device__ __forceinline__ float erf_fast(float x) {
    float ax = fabsf(x);
    float t = __frcp_rn(1.0f + 0.3275911f * ax);
    float y = t * (0.254829592f + t * (-0.284496736f + t * (1.421413741f +
              t * (-1.453152027f + t * 1.061405429f))));
    float r = 1.0f - y * __expf(-ax * ax);
    return copysignf(r, x);
}

__device__ __forceinline__ float gelu_f(float x) {
    return 0.5f * x * (1.0f + erf_fast(x * 0.70710678118654752f));
}

__device__ __forceinline__ void mma16816(float* c, uint32_t a0, uint32_t a1,
                                         uint32_t a2, uint32_t a3,
                                         uint32_t b0, uint32_t b1) {
    asm volatile(
        "mma.sync.aligned.m16n8k16.row.col.f32.f16.f16.f32 "
        "{%0,%1,%2,%3}, {%4,%5,%6,%7}, {%8,%9}, {%0,%1,%2,%3};\n"
        : "+f"(c[0]), "+f"(c[1]), "+f"(c[2]), "+f"(c[3])
        : "r"(a0), "r"(a1), "r"(a2), "r"(a3), "r"(b0), "r"(b1));
}

__device__ __forceinline__ void ldsm_x4(uint32_t& a0, uint32_t& a1, uint32_t& a2,
                                        uint32_t& a3, uint32_t saddr) {
    asm volatile("ldmatrix.sync.aligned.m8n8.x4.shared.b16 {%0,%1,%2,%3}, [%4];\n"
                 : "=r"(a0), "=r"(a1), "=r"(a2), "=r"(a3) : "r"(saddr));
}

__device__ __forceinline__ void ldsm_x2(uint32_t& b0, uint32_t& b1, uint32_t saddr) {
    asm volatile("ldmatrix.sync.aligned.m8n8.x2.shared.b16 {%0,%1}, [%2];\n"
                 : "=r"(b0), "=r"(b1) : "r"(saddr));
}

__device__ __forceinline__ void ldsm_x2t(uint32_t& b0, uint32_t& b1, uint32_t saddr) {
    asm volatile("ldmatrix.sync.aligned.m8n8.x2.trans.shared.b16 {%0,%1}, [%2];\n"
                 : "=r"(b0), "=r"(b1) : "r"(saddr));
}

__device__ __forceinline__ uint32_t smem_u32(const void* p) {
    uint32_t a;
    asm("{ .reg .u64 t; cvta.to.shared.u64 t, %1; cvt.u32.u64 %0, t; }"
        : "=r"(a) : "l"(p));
    return a;
}

// L2-only (no L1 allocation) vector load
__device__ __forceinline__ uint4 ldcg4(const uint4* p) {
    return __ldcg(p);
}

// ---------------- weight packing (A-operand fragment-major, for ODE) ----------------
__global__ void pack_w(const float* __restrict__ W, __half* __restrict__ out, int nM, int K) {
    int idx = blockIdx.x * 256 + threadIdx.x;
    int j    = idx & 7;
    int lane = (idx >> 3) & 31;
    int tile = idx >> 8;
    int mt = tile % nM;
    int ks = tile / nM;
    int gid = lane >> 2, tig = lane & 3;
    int rr = gid + ((j >> 1) & 1) * 8;
    int cc = tig * 2 + (j & 1) + ((j >> 2) & 1) * 8;
    out[idx] = __float2half_rn(W[(size_t)(mt * 16 + rr) * K + ks * 16 + cc]);
}

// ---------------- weight packing (B-operand fragment-major, for hgemm) ----------------
__device__ __forceinline__ void pack_wb_one(const float* W, __half* out, int idx, int N, int K) {
    int h    = idx & 3;
    int lane = (idx >> 2) & 31;
    int rest = idx >> 7;
    int NKS = K / 16;
    int ks = rest % NKS;
    int nt = rest / NKS;
    int n = nt * 8 + (lane >> 2);
    int k = ks * 16 + (lane & 3) * 2 + (h & 1) + ((h >> 1) << 3);
    out[idx] = __float2half_rn(W[(size_t)n * K + k]);
}

__global__ void pack_wb2(const float* __restrict__ Wqkv, const float* __restrict__ Wo) {
    int idx = blockIdx.x * 256 + threadIdx.x;
    if (idx < 3 * D_ * D_) {
        pack_wb_one(Wqkv, g_Wqkvf, idx, 3 * D_, D_);
    } else {
        pack_wb_one(Wo, g_Wof, idx - 3 * D_ * D_, D_, D_);
    }
}

// ---------------- fused persistent ODE kernel (MB=8, 128 CTAs, 512 threads) ----------------
#define MB  8
#define ZP  516
#define ZBP 520
#define HP  264
#define SMEM_ODE (2*MB*ZP*4 + MB*ZBP*2 + 2*MB*HP*2)   // 49792

template<int NM, int NK, bool GELU, bool CG>
__device__ __forceinline__ void gemm_act(
    const __half* __restrict__ Wp, const float* __restrict__ bias,
    const __half* __restrict__ act, int ap,
    __half* __restrict__ out, int op, int warp, int lane)
{
    int gid = lane >> 2, tig = lane & 3;
    #pragma unroll
    for (int mt = warp; mt < NM; mt += 16) {
        float c0[4] = {0.f,0.f,0.f,0.f};
        const uint4* wp = (const uint4*)Wp + mt * 32 + lane;
        const __half* a0p = act + gid * ap + tig * 2;
        #pragma unroll 8
        for (int ks = 0; ks < NK; ks++) {
            uint4 a = CG ? ldcg4(wp + (size_t)ks * NM * 32)
                         : wp[(size_t)ks * NM * 32];
            uint32_t b00 = *(const uint32_t*)(a0p + ks * 16);
            uint32_t b01 = *(const uint32_t*)(a0p + ks * 16 + 8);
            mma16816(c0, a.x, a.y, a.z, a.w, b00, b01);
        }
        int h0 = mt * 16 + gid;
        float bs0 = __ldg(bias + h0);
        float bs1 = __ldg(bias + h0 + 8);
        int r = tig * 2;
        float v;
        v = c0[0] + bs0; if (GELU) v = gelu_f(v); out[(r + 0) * op + h0    ] = __float2half_rn(v);
        v = c0[1] + bs0; if (GELU) v = gelu_f(v); out[(r + 1) * op + h0    ] = __float2half_rn(v);
        v = c0[2] + bs1; if (GELU) v = gelu_f(v); out[(r + 0) * op + h0 + 8] = __float2half_rn(v);
        v = c0[3] + bs1; if (GELU) v = gelu_f(v); out[(r + 1) * op + h0 + 8] = __float2half_rn(v);
    }
}

__device__ __forceinline__ void gemm3_stage(
    const __half* __restrict__ Wp, const float* __restrict__ b3,
    const __half* __restrict__ act,
    float* Z, float* Zacc, __half* Zbf,
    float wcoef, float ccoef, bool doStage, int warp, int lane)
{
    constexpr int NM = 32, NK = 16;
    int gid = lane >> 2, tig = lane & 3;
    float c0[4] = {0.f,0.f,0.f,0.f}, c1[4] = {0.f,0.f,0.f,0.f};
    const uint4* wp0 = (const uint4*)Wp + warp * 32 + lane;
    const uint4* wp1 = wp0 + 16 * 32;
    const __half* a0p = act + gid * HP + tig * 2;
    #pragma unroll 8
    for (int ks = 0; ks < NK; ks++) {
        uint4 a0 = ldcg4(wp0 + (size_t)ks * NM * 32);
        uint4 a1 = ldcg4(wp1 + (size_t)ks * NM * 32);
        uint32_t b00 = *(const uint32_t*)(a0p + ks * 16);
        uint32_t b01 = *(const uint32_t*)(a0p + ks * 16 + 8);
        mma16816(c0, a0.x, a0.y, a0.z, a0.w, b00, b01);
        mma16816(c1, a1.x, a1.y, a1.z, a1.w, b00, b01);
    }
    #pragma unroll
    for (int m = 0; m < 2; m++) {
        const float* cm = m ? c1 : c0;
        int d0 = (warp + m * 16) * 16 + gid;
        float bv0 = __ldg(b3 + d0);
        float bv1 = __ldg(b3 + d0 + 8);
        int r = tig * 2;
        float k;
        #define ODE_DO(cc_, dd_, rr_, bb_)                                          \
            { k = (cc_) + (bb_);                                                    \
              Zacc[(rr_) * ZP + (dd_)] += wcoef * k;                                \
              if (doStage) Zbf[(rr_) * ZBP + (dd_)] =                               \
                  __float2half_rn(Z[(rr_) * ZP + (dd_)] + ccoef * k); }
        ODE_DO(cm[0], d0,     r,     bv0)
        ODE_DO(cm[1], d0,     r + 1, bv0)
        ODE_DO(cm[2], d0 + 8, r,     bv1)
        ODE_DO(cm[3], d0 + 8, r + 1, bv1)
        #undef ODE_DO
    }
}

__global__ void __launch_bounds__(512, 1) ode_kernel(
    const float* __restrict__ zinit, const float* __restrict__ tsteps,
    const float* __restrict__ b1, const float* __restrict__ b2,
    const float* __restrict__ b3)
{
    extern __shared__ char smchar[];
    float*  Z    = (float*)(smchar);
    float*  Zacc = (float*)(smchar + MB * ZP * 4);
    __half* Zbf  = (__half*)(smchar + 2 * MB * ZP * 4);
    __half* H1   = (__half*)(smchar + 2 * MB * ZP * 4 + MB * ZBP * 2);
    __half* H2   = H1 + MB * HP;

    int tid = threadIdx.x, warp = tid >> 5, lane = tid & 31;
    int r0 = blockIdx.x * MB;
    float dt = __ldg(tsteps + 1) - __ldg(tsteps);

    // ---- input-adaptive scale (one warp per row, warps 0-7) ----
    if (warp < MB) {
        int r = warp;
        int sub = lane;
        const float* zr = zinit + (size_t)(r0 + r) * D_;
        float vals[16];
        float s = 0.f, ss = 0.f;
        #pragma unroll
        for (int i = 0; i < 16; i++) {
            float v = zr[sub + i * 32];
            vals[i] = v; s += v; ss += v * v;
        }
        for (int o = 16; o; o >>= 1) {
            s  += __shfl_down_sync(0xffffffffu, s,  o);
            ss += __shfl_down_sync(0xffffffffu, ss, o);
        }
        s  = __shfl_sync(0xffffffffu, s,  0);
        ss = __shfl_sync(0xffffffffu, ss, 0);
        float mean = s * (1.f / D_);
        float var  = (ss - s * mean) * (1.f / (D_ - 1));
        float sc   = sqrtf(ss) / (var + 1e-6f);
        sc = fminf(fmaxf(sc, 0.8f), 1.2f);
        #pragma unroll
        for (int i = 0; i < 16; i++) {
            float z = vals[i] * sc;
            int d = sub + i * 32;
            Z[r * ZP + d] = z;
            Zacc[r * ZP + d] = z;
            Zbf[r * ZBP + d] = __float2half_rn(z);
        }
    }
    __syncthreads();

    const float wc[4] = {1.f, 2.f, 2.f, 1.f};
    const float cc[4] = {0.5f, 0.5f, 1.f, 0.f};

    float zsum[MB];
    #pragma unroll
    for (int j = 0; j < MB; j++) zsum[j] = 0.f;

    for (int t = 0; t < T_; t++) {
        #pragma unroll 1
        for (int e = 0; e < 4; e++) {
            gemm_act<16, 32, true, true >(g_W1p, b1, Zbf, ZBP, H1, HP, warp, lane);
            __syncthreads();
            gemm_act<16, 16, true, false>(g_W2p, b2, H1, HP, H2, HP, warp, lane);
            __syncthreads();
            gemm3_stage(g_W3p, b3, H2, Z, Zacc, Zbf,
                        dt * (1.f / 6.f) * wc[e], dt * cc[e], e < 3, warp, lane);
            __syncthreads();
        }
        #pragma unroll
        for (int j = 0; j < MB; j++) {
            int i = tid + j * 512;
            int r = i >> 9, d = i & 511;
            float z = Zacc[r * ZP + d];
            if (isnan(z)) z = 0.f;
            Z[r * ZP + d] = z;
            Zacc[r * ZP + d] = z;
            Zbf[r * ZBP + d] = __float2half_rn(z);
            zsum[j] += z;
            g_zstack[((size_t)(r0 + r) * T_ + t) * D_ + d] = z;
        }
        __syncthreads();
    }

    // ---- write zmean (fused; same t-ascending summation order) ----
    #pragma unroll
    for (int j = 0; j < MB; j++) {
        int i = tid + j * 512;
        int r = i >> 9, d = i & 511;
        g_zmean[(size_t)(r0 + r) * D_ + d] = zsum[j] * (1.0f / T_);
    }
}

// ---------------- hgemm + optional fused z_dc A-prep ----------------
#define AP 520
#define SMEM_HG (128*AP*2)

template<int NTOT, int MODE, typename OT>
__global__ void __launch_bounds__(256, 1) hgemm(
    const __half* __restrict__ Act,
    const float* __restrict__ zstack, const float* __restrict__ zmean,
    const float* __restrict__ zinit,
    const __half* __restrict__ Wf,
    const float* __restrict__ bias, OT* __restrict__ C)
{
    extern __shared__ __half As[];
    int tid = threadIdx.x, warp = tid >> 5, lane = tid & 31;
    int m0 = blockIdx.x * 128;

    if (MODE == 0) {
        for (int i = tid; i < 128 * 64; i += 256) {
            int r = i >> 6, c = i & 63;
            *(uint4*)&As[r * AP + c * 8] =
                *(const uint4*)&Act[(size_t)(m0 + r) * 512 + c * 8];
        }
    } else {
        for (int i = tid; i < 128 * 128; i += 256) {
            int r = i >> 7, c = (i & 127) * 4;
            int row = m0 + r;
            int b = row >> 6;
            float4 zs = *(const float4*)&zstack[(size_t)row * 512 + c];
            float4 zm = *(const float4*)&zmean[(size_t)b * 512 + c];
            float4 zi = *(const float4*)&zinit[(size_t)b * 512 + c];
            __half2 h01 = __floats2half2_rn(zs.x - 0.05f * (zm.x - zi.x),
                                            zs.y - 0.05f * (zm.y - zi.y));
            __half2 h23 = __floats2half2_rn(zs.z - 0.05f * (zm.z - zi.z),
                                            zs.w - 0.05f * (zm.w - zi.w));
            uint2 u;
            u.x = *(uint32_t*)&h01; u.y = *(uint32_t*)&h23;
            *(uint2*)&As[r * AP + c] = u;
        }
    }
    __syncthreads();

    int mw = warp * 16;
    int arow = mw + (lane & 7) + ((lane >> 3) & 1) * 8;
    int acol = ((lane >> 4) & 1) * 8;
    uint32_t abase = smem_u32(As) + (arow * AP + acol) * 2;

    int r = lane >> 2, cpair = (lane & 3) * 2;

    for (int ng = 0; ng < NTOT / 64; ng++) {
        float acc[8][4];
        #pragma unroll
        for (int j = 0; j < 8; j++)
            #pragma unroll
            for (int q = 0; q < 4; q++) acc[j][q] = 0.f;

        const uint2* wbase = (const uint2*)Wf + ((size_t)ng * 8 * 32) * 32 + lane;
        #pragma unroll 4
        for (int ks = 0; ks < 32; ks++) {
            uint32_t a0, a1, a2, a3;
            ldsm_x4(a0, a1, a2, a3, abase + ks * 32);
            #pragma unroll
            for (int j = 0; j < 8; j++) {
                uint2 b = wbase[((size_t)j * 32 + ks) * 32];
                mma16816(acc[j], a0, a1, a2, a3, b.x, b.y);
            }
        }
        #pragma unroll
        for (int j = 0; j < 8; j++) {
            int n = ng * 64 + j * 8 + cpair;
            float bv0 = __ldg(bias + n), bv1 = __ldg(bias + n + 1);
            float v00 = acc[j][0] + bv0, v01 = acc[j][1] + bv1;
            float v10 = acc[j][2] + bv0, v11 = acc[j][3] + bv1;
            if (sizeof(OT) == 2) {
                __half2 lo = __floats2half2_rn(v00, v01);
                __half2 hi = __floats2half2_rn(v10, v11);
                *(uint32_t*)&C[(size_t)(m0 + mw + r)     * NTOT + n] = *(uint32_t*)&lo;
                *(uint32_t*)&C[(size_t)(m0 + mw + r + 8) * NTOT + n] = *(uint32_t*)&hi;
            } else {
                *(float2*)&C[(size_t)(m0 + mw + r)     * NTOT + n] = make_float2(v00, v01);
                *(float2*)&C[(size_t)(m0 + mw + r + 8) * NTOT + n] = make_float2(v10, v11);
            }
        }
    }
}

// ---------------- tensor-core attention: per (b,h), 128 threads ----------------
#define VP 136                               // Q/K/V fp16 pitch
#define PP 72                                // P fp16 pitch
#define AT_QS 0
#define AT_KS (64*VP*2)                      // 17408
#define AT_VS (2*64*VP*2)                    // 34816
#define AT_S  (3*64*VP*2)                    // 52224 (fp32, pitch 65)
#define AT_PS (AT_S + 64*65*4)               // 68864
#define ATTN_SMEM_BYTES (AT_PS + 64*PP*2)    // 78080

__global__ void __launch_bounds__(128, 1) attn_kernel() {
    extern __shared__ char sm[];
    __half* Qs = (__half*)(sm + AT_QS);
    __half* Ks = (__half*)(sm + AT_KS);
    __half* Vs = (__half*)(sm + AT_VS);
    float*  S  = (float*)(sm + AT_S);
    __half* Ps = (__half*)(sm + AT_PS);

    int tid = threadIdx.x, warp = tid >> 5, lane = tid & 31;
    int bh = blockIdx.x;
    int b = bh >> 2, h = bh & 3;
    int gid = lane >> 2, tig = lane & 3;

    // ---- load Q,K,V fp16 directly ----
    for (int idx = tid; idx < 64 * 16; idx += 128) {
        int t = idx >> 4, c = (idx & 15) * 8;
        size_t base = ((size_t)(b * T_ + t)) * (3 * D_) + h * HD_ + c;
        #pragma unroll
        for (int w = 0; w < 3; w++) {
            *(uint4*)&((__half*)(sm + w * 64 * VP * 2))[t * VP + c] =
                *(const uint4*)&g_qkvh[base + (size_t)w * D_];
        }
    }
    __syncthreads();

    // ---- scores: warp computes rows [warp*16, warp*16+16) x 64 ----
    int m0 = warp * 16;
    {
        uint32_t qbase = smem_u32(Qs) +
            ((m0 + (lane & 7) + ((lane >> 3) & 1) * 8) * VP + ((lane >> 4) & 1) * 8) * 2;
        uint32_t kbase = smem_u32(Ks) +
            (((lane & 15) & 7) * VP + (((lane & 15) >> 3)) * 8) * 2;
        float c[8][4];
        #pragma unroll
        for (int j = 0; j < 8; j++)
            #pragma unroll
            for (int q = 0; q < 4; q++) c[j][q] = 0.f;
        #pragma unroll
        for (int ks = 0; ks < 8; ks++) {
            uint32_t a0, a1, a2, a3;
            ldsm_x4(a0, a1, a2, a3, qbase + ks * 32);
            #pragma unroll
            for (int j = 0; j < 8; j++) {
                uint32_t b0, b1;
                ldsm_x2(b0, b1, kbase + (j * 8 * VP + ks * 16) * 2);
                mma16816(c[j], a0, a1, a2, a3, b0, b1);
            }
        }
        const float sc = 0.08838834764831845f;   // 1/sqrt(128)
        #pragma unroll
        for (int j = 0; j < 8; j++) {
            int col = j * 8 + tig * 2;
            S[(m0 + gid)     * 65 + col]     = c[j][0] * sc;
            S[(m0 + gid)     * 65 + col + 1] = c[j][1] * sc;
            S[(m0 + gid + 8) * 65 + col]     = c[j][2] * sc;
            S[(m0 + gid + 8) * 65 + col + 1] = c[j][3] * sc;
        }
    }
    __syncthreads();

    // ---- softmax: 2 threads per row ----
    {
        int r = tid >> 1, hf = tid & 1;
        float* Srow = S + r * 65 + hf * 32;
        float lmax = -1e30f;
        #pragma unroll
        for (int j = 0; j < 32; j++) lmax = fmaxf(lmax, Srow[j]);
        lmax = fmaxf(lmax, __shfl_xor_sync(0xffffffffu, lmax, 1));
        float lsum = 0.f;
        #pragma unroll
        for (int j = 0; j < 32; j++) {
            float e = expf(Srow[j] - lmax);
            Srow[j] = e;
            lsum += e;
        }
        lsum += __shfl_xor_sync(0xffffffffu, lsum, 1);
        float inv = 1.0f / lsum;
        __half* Prow = Ps + r * PP + hf * 32;
        #pragma unroll
        for (int j = 0; j < 16; j++) {
            __half2 p = __floats2half2_rn(Srow[j * 2] * inv, Srow[j * 2 + 1] * inv);
            *(uint32_t*)&Prow[j * 2] = *(uint32_t*)&p;
        }
    }
    __syncthreads();

    // ---- ctx = P @ V : warp computes rows m0..m0+15 x 128, two 64-col halves ----
    {
        uint32_t pbase = smem_u32(Ps) +
            ((m0 + (lane & 7) + ((lane >> 3) & 1) * 8) * PP + ((lane >> 4) & 1) * 8) * 2;
        uint32_t vbase = smem_u32(Vs) + ((lane & 15) * VP) * 2;
        #pragma unroll
        for (int dh = 0; dh < 2; dh++) {
            float c[8][4];
            #pragma unroll
            for (int j = 0; j < 8; j++)
                #pragma unroll
                for (int q = 0; q < 4; q++) c[j][q] = 0.f;
            #pragma unroll
            for (int ks = 0; ks < 4; ks++) {
                uint32_t a0, a1, a2, a3;
                ldsm_x4(a0, a1, a2, a3, pbase + ks * 32);
                #pragma unroll
                for (int j = 0; j < 8; j++) {
                    int d0 = dh * 64 + j * 8;
                    uint32_t b0, b1;
                    ldsm_x2t(b0, b1, vbase + (ks * 16 * VP + d0) * 2);
                    mma16816(c[j], a0, a1, a2, a3, b0, b1);
                }
            }
            #pragma unroll
            for (int j = 0; j < 8; j++) {
                int d0 = dh * 64 + j * 8 + tig * 2;
                size_t base0 = ((size_t)(b * T_ + m0 + gid))     * D_ + h * HD_ + d0;
                size_t base1 = ((size_t)(b * T_ + m0 + gid + 8)) * D_ + h * HD_ + d0;
                __half2 lo = __floats2half2_rn(c[j][0], c[j][1]);
                __half2 hi = __floats2half2_rn(c[j][2], c[j][3]);
                *(uint32_t*)&g_ctxh[base0] = *(uint32_t*)&lo;
                *(uint32_t*)&g_ctxh[base1] = *(uint32_t*)&hi;
            }
        }
    }
}

// ---------------- residual + LayerNorm ----------------
__global__ void ln_kernel(const float* __restrict__ zinit, const float* __restrict__ gamma,
                          const float* __restrict__ beta, float* __restrict__ out) {
    int row = blockIdx.x;
    int b = row >> 6;
    int tid = threadIdx.x;
    const float* ao = g_atto;
    float x[4];
    float s = 0.f, ss = 0.f;
    #pragma unroll
    for (int q = 0; q < 4; q++) {
        int d = tid + q * 128;
        float zs  = g_zstack[(size_t)row * D_ + d];
        float zdc = zs - 0.05f * (g_zmean[(size_t)b * D_ + d] - zinit[(size_t)b * D_ + d]);
        float v = zdc + ao[(size_t)row * D_ + d];
        x[q] = v; s += v; ss += v * v;
    }
    __shared__ float rs[4], rss[4];
    for (int o = 16; o; o >>= 1) {
        s  += __shfl_down_sync(0xffffffffu, s,  o);
        ss += __shfl_down_sync(0xffffffffu, ss, o);
    }
    if ((tid & 31) == 0) { rs[tid >> 5] = s; rss[tid >> 5] = ss; }
    __syncthreads();
    float sum   = rs[0] + rs[1] + rs[2] + rs[3];
    float sumsq = rss[0] + rss[1] + rss[2] + rss[3];
    float mean = sum * (1.0f / D_);
    float var  = sumsq * (1.0f / D_) - mean * mean;
    float inv  = rsqrtf(var + 1e-5f);
    #pragma unroll
    for (int q = 0; q < 4; q++) {
        int d = tid + q * 128;
        float o = (x[q] - mean) * inv * gamma[d] + beta[d];
        if (isnan(o)) o = 0.f;
        out[(size_t)row * D_ + d] = o;
    }
}

// ---------------- host orchestration ----------------
extern "C" void kernel_launch(void* const* d_in, const int* in_sizes, int n_in,
                              void* d_out, int out_size)
{
    const float* z_init = (const float*)d_in[0];
    const float* tsteps = (const float*)d_in[1];
    const float* W1     = (const float*)d_in[2];
    const float* b1     = (const float*)d_in[3];
    const float* W2     = (const float*)d_in[4];
    const float* b2     = (const float*)d_in[5];
    const float* W3     = (const float*)d_in[6];
    const float* b3     = (const float*)d_in[7];
    const float* Wqkv   = (const float*)d_in[8];
    const float* bqkv   = (const float*)d_in[9];
    const float* Wo     = (const float*)d_in[10];
    const float* bo     = (const float*)d_in[11];
    const float* gamma  = (const float*)d_in[12];
    const float* beta   = (const float*)d_in[13];

    float *zstack, *zmean, *atto;
    __half *w1p, *w2p, *w3p, *wqkvf, *wof, *ctxh, *qkvh;
    cudaGetSymbolAddress((void**)&zstack, g_zstack);
    cudaGetSymbolAddress((void**)&zmean,  g_zmean);
    cudaGetSymbolAddress((void**)&atto,   g_atto);
    cudaGetSymbolAddress((void**)&qkvh,   g_qkvh);
    cudaGetSymbolAddress((void**)&w1p,    g_W1p);
    cudaGetSymbolAddress((void**)&w2p,    g_W2p);
    cudaGetSymbolAddress((void**)&w3p,    g_W3p);
    cudaGetSymbolAddress((void**)&wqkvf,  g_Wqkvf);
    cudaGetSymbolAddress((void**)&wof,    g_Wof);
    cudaGetSymbolAddress((void**)&ctxh,   g_ctxh);

    cudaFuncSetAttribute(attn_kernel, cudaFuncAttributeMaxDynamicSharedMemorySize,
                         ATTN_SMEM_BYTES);
    cudaFuncSetAttribute(ode_kernel, cudaFuncAttributeMaxDynamicSharedMemorySize,
                         SMEM_ODE);
    cudaFuncSetAttribute(hgemm<3*D_, 1, __half>, cudaFuncAttributeMaxDynamicSharedMemorySize,
                         SMEM_HG);
    cudaFuncSetAttribute(hgemm<D_, 0, float>, cudaFuncAttributeMaxDynamicSharedMemorySize,
                         SMEM_HG);

    // 0) pack weights
    pack_w<<<(HID_ * D_) / 256, 256>>>(W1, w1p, HID_ / 16, D_);
    pack_w<<<(HID_ * HID_) / 256, 256>>>(W2, w2p, HID_ / 16, HID_);
    pack_w<<<(D_ * HID_) / 256, 256>>>(W3, w3p, D_ / 16, HID_);
    pack_wb2<<<(4 * D_ * D_) / 256, 256>>>(Wqkv, Wo);

    // 1) fused scale + full RK4 trajectory + zmean (128 CTAs)
    ode_kernel<<<B_ / MB, 512, SMEM_ODE>>>(z_init, tsteps, b1, b2, b3);

    // 2) QKV projection (fused z_dc prep, fp16 output)
    hgemm<3*D_, 1, __half><<<BT_ / 128, 256, SMEM_HG>>>(
        nullptr, zstack, zmean, z_init, wqkvf, bqkv, qkvh);

    // 3) tensor-core attention per (b,h)
    attn_kernel<<<B_ * NH_, 128, ATTN_SMEM_BYTES>>>();

    // 4) output projection (att_out fp32)
    hgemm<D_, 0, float><<<BT_ / 128, 256, SMEM_HG>>>(
        ctxh, nullptr, nullptr, nullptr, wof, bo, atto);

    // 5) residual + LayerNorm
    ln_kernel<<<BT_, 128>>>(z_init, gamma, beta, (float*)d_out);
}

// round 15
// speedup vs baseline: 1.4377x; 1.0180x over previous
#include <cuda_runtime.h>
#include <cuda_fp16.h>
#include <stdint.h>
#include <math.h>

#define B_   1024
#define T_   64
#define D_   512
#define HID_ 256
#define NH_  4
#define HD_  128
#define BT_  (B_*T_)

// ---------------- scratch ----------------
__device__ float  g_zstack[(size_t)BT_*D_];   // [B,T,D] trajectory (fp32)
__device__ float  g_zmean[B_*D_];             // mean over T
__device__ __half g_qkvh[(size_t)BT_*3*D_];   // qkv fp16
__device__ float  g_atto[(size_t)BT_*D_];     // att_out fp32
__device__ __half g_ctxh[(size_t)BT_*D_];     // attention context fp16
// packed fp16 fragment-major weights
__device__ __half g_W1p[HID_*D_];
__device__ __half g_W2p[HID_*HID_];
__device__ __half g_W3p[D_*HID_];
__device__ __half g_Wqkvf[3*D_*D_];
__device__ __half g_Wof[D_*D_];

// ---------------- helpers ----------------
__device__ __forceinline__ float gelu_f(float x) {
    return 0.5f * x * (1.0f + erff(x * 0.70710678118654752f));
}

__device__ __forceinline__ void mma16816(float* c, uint32_t a0, uint32_t a1,
                                         uint32_t a2, uint32_t a3,
                                         uint32_t b0, uint32_t b1) {
    asm volatile(
        "mma.sync.aligned.m16n8k16.row.col.f32.f16.f16.f32 "
        "{%0,%1,%2,%3}, {%4,%5,%6,%7}, {%8,%9}, {%0,%1,%2,%3};\n"
        : "+f"(c[0]), "+f"(c[1]), "+f"(c[2]), "+f"(c[3])
        : "r"(a0), "r"(a1), "r"(a2), "r"(a3), "r"(b0), "r"(b1));
}

__device__ __forceinline__ void ldsm_x4(uint32_t& a0, uint32_t& a1, uint32_t& a2,
                                        uint32_t& a3, uint32_t saddr) {
    asm volatile("ldmatrix.sync.aligned.m8n8.x4.shared.b16 {%0,%1,%2,%3}, [%4];\n"
                 : "=r"(a0), "=r"(a1), "=r"(a2), "=r"(a3) : "r"(saddr));
}

__device__ __forceinline__ void ldsm_x2(uint32_t& b0, uint32_t& b1, uint32_t saddr) {
    asm volatile("ldmatrix.sync.aligned.m8n8.x2.shared.b16 {%0,%1}, [%2];\n"
                 : "=r"(b0), "=r"(b1) : "r"(saddr));
}

__device__ __forceinline__ void ldsm_x2t(uint32_t& b0, uint32_t& b1, uint32_t saddr) {
    asm volatile("ldmatrix.sync.aligned.m8n8.x2.trans.shared.b16 {%0,%1}, [%2];\n"
                 : "=r"(b0), "=r"(b1) : "r"(saddr));
}

__device__ __forceinline__ uint32_t smem_u32(const void* p) {
    uint32_t a;
    asm("{ .reg .u64 t; cvta.to.shared.u64 t, %1; cvt.u32.u64 %0, t; }"
        : "=r"(a) : "l"(p));
    return a;
}

// L2-only (no L1 allocation) vector load — intrinsic (compiler-schedulable)
__device__ __forceinline__ uint4 ldcg4(const uint4* p) {
    return __ldcg(p);
}

// ---------------- weight packing (A-operand fragment-major, for ODE) ----------------
__global__ void pack_w(const float* __restrict__ W, __half* __restrict__ out, int nM, int K) {
    int idx = blockIdx.x * 256 + threadIdx.x;
    int j    = idx & 7;
    int lane = (idx >> 3) & 31;
    int tile = idx >> 8;
    int mt = tile % nM;
    int ks = tile / nM;
    int gid = lane >> 2, tig = lane & 3;
    int rr = gid + ((j >> 1) & 1) * 8;
    int cc = tig * 2 + (j & 1) + ((j >> 2) & 1) * 8;
    out[idx] = __float2half_rn(W[(size_t)(mt * 16 + rr) * K + ks * 16 + cc]);
}

// ---------------- weight packing (B-operand fragment-major, for hgemm) ----------------
__device__ __forceinline__ void pack_wb_one(const float* W, __half* out, int idx, int N, int K) {
    int h    = idx & 3;
    int lane = (idx >> 2) & 31;
    int rest = idx >> 7;
    int NKS = K / 16;
    int ks = rest % NKS;
    int nt = rest / NKS;
    int n = nt * 8 + (lane >> 2);
    int k = ks * 16 + (lane & 3) * 2 + (h & 1) + ((h >> 1) << 3);
    out[idx] = __float2half_rn(W[(size_t)n * K + k]);
}

__global__ void pack_wb2(const float* __restrict__ Wqkv, const float* __restrict__ Wo) {
    int idx = blockIdx.x * 256 + threadIdx.x;
    if (idx < 3 * D_ * D_) {
        pack_wb_one(Wqkv, g_Wqkvf, idx, 3 * D_, D_);
    } else {
        pack_wb_one(Wo, g_Wof, idx - 3 * D_ * D_, D_, D_);
    }
}

// ---------------- fused persistent ODE kernel (MB=8, 128 CTAs, 512 threads) ----------------
#define MB  8
#define ZP  516
#define ZBP 520
#define HP  264
#define SMEM_ODE (2*MB*ZP*4 + MB*ZBP*2 + 2*MB*HP*2)   // 49792

template<int NM, int NK, bool GELU, bool CG>
__device__ __forceinline__ void gemm_act(
    const __half* __restrict__ Wp, const float* __restrict__ bias,
    const __half* __restrict__ act, int ap,
    __half* __restrict__ out, int op, int warp, int lane)
{
    int gid = lane >> 2, tig = lane & 3;
    #pragma unroll
    for (int mt = warp; mt < NM; mt += 16) {
        float c0[4] = {0.f,0.f,0.f,0.f};
        const uint4* wp = (const uint4*)Wp + mt * 32 + lane;
        const __half* a0p = act + gid * ap + tig * 2;
        #pragma unroll 8
        for (int ks = 0; ks < NK; ks++) {
            uint4 a = CG ? ldcg4(wp + (size_t)ks * NM * 32)
                         : wp[(size_t)ks * NM * 32];
            uint32_t b00 = *(const uint32_t*)(a0p + ks * 16);
            uint32_t b01 = *(const uint32_t*)(a0p + ks * 16 + 8);
            mma16816(c0, a.x, a.y, a.z, a.w, b00, b01);
        }
        int h0 = mt * 16 + gid;
        float bs0 = __ldg(bias + h0);
        float bs1 = __ldg(bias + h0 + 8);
        int r = tig * 2;
        float v;
        v = c0[0] + bs0; if (GELU) v = gelu_f(v); out[(r + 0) * op + h0    ] = __float2half_rn(v);
        v = c0[1] + bs0; if (GELU) v = gelu_f(v); out[(r + 1) * op + h0    ] = __float2half_rn(v);
        v = c0[2] + bs1; if (GELU) v = gelu_f(v); out[(r + 0) * op + h0 + 8] = __float2half_rn(v);
        v = c0[3] + bs1; if (GELU) v = gelu_f(v); out[(r + 1) * op + h0 + 8] = __float2half_rn(v);
    }
}

__device__ __forceinline__ void gemm3_stage(
    const __half* __restrict__ Wp, const float* __restrict__ b3,
    const __half* __restrict__ act,
    float* Z, float* Zacc, __half* Zbf,
    float wcoef, float ccoef, bool doStage, int warp, int lane)
{
    constexpr int NM = 32, NK = 16;
    int gid = lane >> 2, tig = lane & 3;
    float c0[4] = {0.f,0.f,0.f,0.f}, c1[4] = {0.f,0.f,0.f,0.f};
    const uint4* wp0 = (const uint4*)Wp + warp * 32 + lane;
    const uint4* wp1 = wp0 + 16 * 32;
    const __half* a0p = act + gid * HP + tig * 2;
    #pragma unroll 8
    for (int ks = 0; ks < NK; ks++) {
        uint4 a0 = ldcg4(wp0 + (size_t)ks * NM * 32);
        uint4 a1 = ldcg4(wp1 + (size_t)ks * NM * 32);
        uint32_t b00 = *(const uint32_t*)(a0p + ks * 16);
        uint32_t b01 = *(const uint32_t*)(a0p + ks * 16 + 8);
        mma16816(c0, a0.x, a0.y, a0.z, a0.w, b00, b01);
        mma16816(c1, a1.x, a1.y, a1.z, a1.w, b00, b01);
    }
    #pragma unroll
    for (int m = 0; m < 2; m++) {
        const float* cm = m ? c1 : c0;
        int d0 = (warp + m * 16) * 16 + gid;
        float bv0 = __ldg(b3 + d0);
        float bv1 = __ldg(b3 + d0 + 8);
        int r = tig * 2;
        float k;
        #define ODE_DO(cc_, dd_, rr_, bb_)                                          \
            { k = (cc_) + (bb_);                                                    \
              Zacc[(rr_) * ZP + (dd_)] += wcoef * k;                                \
              if (doStage) Zbf[(rr_) * ZBP + (dd_)] =                               \
                  __float2half_rn(Z[(rr_) * ZP + (dd_)] + ccoef * k); }
        ODE_DO(cm[0], d0,     r,     bv0)
        ODE_DO(cm[1], d0,     r + 1, bv0)
        ODE_DO(cm[2], d0 + 8, r,     bv1)
        ODE_DO(cm[3], d0 + 8, r + 1, bv1)
        #undef ODE_DO
    }
}

__global__ void __launch_bounds__(512, 1) ode_kernel(
    const float* __restrict__ zinit, const float* __restrict__ tsteps,
    const float* __restrict__ b1, const float* __restrict__ b2,
    const float* __restrict__ b3)
{
    extern __shared__ char smchar[];
    float*  Z    = (float*)(smchar);
    float*  Zacc = (float*)(smchar + MB * ZP * 4);
    __half* Zbf  = (__half*)(smchar + 2 * MB * ZP * 4);
    __half* H1   = (__half*)(smchar + 2 * MB * ZP * 4 + MB * ZBP * 2);
    __half* H2   = H1 + MB * HP;

    int tid = threadIdx.x, warp = tid >> 5, lane = tid & 31;
    int r0 = blockIdx.x * MB;
    float dt = __ldg(tsteps + 1) - __ldg(tsteps);

    // ---- input-adaptive scale (one warp per row, warps 0-7) ----
    if (warp < MB) {
        int r = warp;
        int sub = lane;
        const float* zr = zinit + (size_t)(r0 + r) * D_;
        float vals[16];
        float s = 0.f, ss = 0.f;
        #pragma unroll
        for (int i = 0; i < 16; i++) {
            float v = zr[sub + i * 32];
            vals[i] = v; s += v; ss += v * v;
        }
        for (int o = 16; o; o >>= 1) {
            s  += __shfl_down_sync(0xffffffffu, s,  o);
            ss += __shfl_down_sync(0xffffffffu, ss, o);
        }
        s  = __shfl_sync(0xffffffffu, s,  0);
        ss = __shfl_sync(0xffffffffu, ss, 0);
        float mean = s * (1.f / D_);
        float var  = (ss - s * mean) * (1.f / (D_ - 1));
        float sc   = sqrtf(ss) / (var + 1e-6f);
        sc = fminf(fmaxf(sc, 0.8f), 1.2f);
        #pragma unroll
        for (int i = 0; i < 16; i++) {
            float z = vals[i] * sc;
            int d = sub + i * 32;
            Z[r * ZP + d] = z;
            Zacc[r * ZP + d] = z;
            Zbf[r * ZBP + d] = __float2half_rn(z);
        }
    }
    __syncthreads();

    const float wc[4] = {1.f, 2.f, 2.f, 1.f};
    const float cc[4] = {0.5f, 0.5f, 1.f, 0.f};

    float zsum[MB];
    #pragma unroll
    for (int j = 0; j < MB; j++) zsum[j] = 0.f;

    for (int t = 0; t < T_; t++) {
        #pragma unroll 1
        for (int e = 0; e < 4; e++) {
            gemm_act<16, 32, true, true >(g_W1p, b1, Zbf, ZBP, H1, HP, warp, lane);
            __syncthreads();
            gemm_act<16, 16, true, false>(g_W2p, b2, H1, HP, H2, HP, warp, lane);
            __syncthreads();
            gemm3_stage(g_W3p, b3, H2, Z, Zacc, Zbf,
                        dt * (1.f / 6.f) * wc[e], dt * cc[e], e < 3, warp, lane);
            __syncthreads();
        }
        #pragma unroll
        for (int j = 0; j < MB; j++) {
            int i = tid + j * 512;
            int r = i >> 9, d = i & 511;
            float z = Zacc[r * ZP + d];
            if (isnan(z)) z = 0.f;
            Z[r * ZP + d] = z;
            Zacc[r * ZP + d] = z;
            Zbf[r * ZBP + d] = __float2half_rn(z);
            zsum[j] += z;
            g_zstack[((size_t)(r0 + r) * T_ + t) * D_ + d] = z;
        }
        __syncthreads();
    }

    // ---- write zmean (fused; same t-ascending summation order) ----
    #pragma unroll
    for (int j = 0; j < MB; j++) {
        int i = tid + j * 512;
        int r = i >> 9, d = i & 511;
        g_zmean[(size_t)(r0 + r) * D_ + d] = zsum[j] * (1.0f / T_);
    }
}

// ---------------- hgemm + optional fused z_dc A-prep ----------------
#define AP 520
#define SMEM_HG (128*AP*2)

template<int NTOT, int MODE, typename OT>
__global__ void __launch_bounds__(256, 1) hgemm(
    const __half* __restrict__ Act,
    const float* __restrict__ zstack, const float* __restrict__ zmean,
    const float* __restrict__ zinit,
    const __half* __restrict__ Wf,
    const float* __restrict__ bias, OT* __restrict__ C)
{
    extern __shared__ __half As[];
    int tid = threadIdx.x, warp = tid >> 5, lane = tid & 31;
    int m0 = blockIdx.x * 128;

    if (MODE == 0) {
        for (int i = tid; i < 128 * 64; i += 256) {
            int r = i >> 6, c = i & 63;
            *(uint4*)&As[r * AP + c * 8] =
                *(const uint4*)&Act[(size_t)(m0 + r) * 512 + c * 8];
        }
    } else {
        for (int i = tid; i < 128 * 128; i += 256) {
            int r = i >> 7, c = (i & 127) * 4;
            int row = m0 + r;
            int b = row >> 6;
            float4 zs = *(const float4*)&zstack[(size_t)row * 512 + c];
            float4 zm = *(const float4*)&zmean[(size_t)b * 512 + c];
            float4 zi = *(const float4*)&zinit[(size_t)b * 512 + c];
            __half2 h01 = __floats2half2_rn(zs.x - 0.05f * (zm.x - zi.x),
                                            zs.y - 0.05f * (zm.y - zi.y));
            __half2 h23 = __floats2half2_rn(zs.z - 0.05f * (zm.z - zi.z),
                                            zs.w - 0.05f * (zm.w - zi.w));
            uint2 u;
            u.x = *(uint32_t*)&h01; u.y = *(uint32_t*)&h23;
            *(uint2*)&As[r * AP + c] = u;
        }
    }
    __syncthreads();

    int mw = warp * 16;
    int arow = mw + (lane & 7) + ((lane >> 3) & 1) * 8;
    int acol = ((lane >> 4) & 1) * 8;
    uint32_t abase = smem_u32(As) + (arow * AP + acol) * 2;

    int r = lane >> 2, cpair = (lane & 3) * 2;

    for (int ng = 0; ng < NTOT / 64; ng++) {
        float acc[8][4];
        #pragma unroll
        for (int j = 0; j < 8; j++)
            #pragma unroll
            for (int q = 0; q < 4; q++) acc[j][q] = 0.f;

        const uint2* wbase = (const uint2*)Wf + ((size_t)ng * 8 * 32) * 32 + lane;
        #pragma unroll 4
        for (int ks = 0; ks < 32; ks++) {
            uint32_t a0, a1, a2, a3;
            ldsm_x4(a0, a1, a2, a3, abase + ks * 32);
            #pragma unroll
            for (int j = 0; j < 8; j++) {
                uint2 b = wbase[((size_t)j * 32 + ks) * 32];
                mma16816(acc[j], a0, a1, a2, a3, b.x, b.y);
            }
        }
        #pragma unroll
        for (int j = 0; j < 8; j++) {
            int n = ng * 64 + j * 8 + cpair;
            float bv0 = __ldg(bias + n), bv1 = __ldg(bias + n + 1);
            float v00 = acc[j][0] + bv0, v01 = acc[j][1] + bv1;
            float v10 = acc[j][2] + bv0, v11 = acc[j][3] + bv1;
            if (sizeof(OT) == 2) {
                __half2 lo = __floats2half2_rn(v00, v01);
                __half2 hi = __floats2half2_rn(v10, v11);
                *(uint32_t*)&C[(size_t)(m0 + mw + r)     * NTOT + n] = *(uint32_t*)&lo;
                *(uint32_t*)&C[(size_t)(m0 + mw + r + 8) * NTOT + n] = *(uint32_t*)&hi;
            } else {
                *(float2*)&C[(size_t)(m0 + mw + r)     * NTOT + n] = make_float2(v00, v01);
                *(float2*)&C[(size_t)(m0 + mw + r + 8) * NTOT + n] = make_float2(v10, v11);
            }
        }
    }
}

// ---------------- tensor-core attention: per (b,h), 128 threads ----------------
#define VP 136                               // Q/K/V fp16 pitch
#define PP 72                                // P fp16 pitch
#define AT_QS 0
#define AT_KS (64*VP*2)                      // 17408
#define AT_VS (2*64*VP*2)                    // 34816
#define AT_S  (3*64*VP*2)                    // 52224 (fp32, pitch 65)
#define AT_PS (AT_S + 64*65*4)               // 68864
#define ATTN_SMEM_BYTES (AT_PS + 64*PP*2)    // 78080

__global__ void __launch_bounds__(128, 1) attn_kernel() {
    extern __shared__ char sm[];
    __half* Qs = (__half*)(sm + AT_QS);
    __half* Ks = (__half*)(sm + AT_KS);
    __half* Vs = (__half*)(sm + AT_VS);
    float*  S  = (float*)(sm + AT_S);
    __half* Ps = (__half*)(sm + AT_PS);

    int tid = threadIdx.x, warp = tid >> 5, lane = tid & 31;
    int bh = blockIdx.x;
    int b = bh >> 2, h = bh & 3;
    int gid = lane >> 2, tig = lane & 3;

    // ---- load Q,K,V fp16 directly ----
    for (int idx = tid; idx < 64 * 16; idx += 128) {
        int t = idx >> 4, c = (idx & 15) * 8;
        size_t base = ((size_t)(b * T_ + t)) * (3 * D_) + h * HD_ + c;
        #pragma unroll
        for (int w = 0; w < 3; w++) {
            *(uint4*)&((__half*)(sm + w * 64 * VP * 2))[t * VP + c] =
                *(const uint4*)&g_qkvh[base + (size_t)w * D_];
        }
    }
    __syncthreads();

    // ---- scores: warp computes rows [warp*16, warp*16+16) x 64 ----
    int m0 = warp * 16;
    {
        uint32_t qbase = smem_u32(Qs) +
            ((m0 + (lane & 7) + ((lane >> 3) & 1) * 8) * VP + ((lane >> 4) & 1) * 8) * 2;
        uint32_t kbase = smem_u32(Ks) +
            (((lane & 15) & 7) * VP + (((lane & 15) >> 3)) * 8) * 2;
        float c[8][4];
        #pragma unroll
        for (int j = 0; j < 8; j++)
            #pragma unroll
            for (int q = 0; q < 4; q++) c[j][q] = 0.f;
        #pragma unroll
        for (int ks = 0; ks < 8; ks++) {
            uint32_t a0, a1, a2, a3;
            ldsm_x4(a0, a1, a2, a3, qbase + ks * 32);
            #pragma unroll
            for (int j = 0; j < 8; j++) {
                uint32_t b0, b1;
                ldsm_x2(b0, b1, kbase + (j * 8 * VP + ks * 16) * 2);
                mma16816(c[j], a0, a1, a2, a3, b0, b1);
            }
        }
        const float sc = 0.08838834764831845f;   // 1/sqrt(128)
        #pragma unroll
        for (int j = 0; j < 8; j++) {
            int col = j * 8 + tig * 2;
            S[(m0 + gid)     * 65 + col]     = c[j][0] * sc;
            S[(m0 + gid)     * 65 + col + 1] = c[j][1] * sc;
            S[(m0 + gid + 8) * 65 + col]     = c[j][2] * sc;
            S[(m0 + gid + 8) * 65 + col + 1] = c[j][3] * sc;
        }
    }
    __syncthreads();

    // ---- softmax: 2 threads per row ----
    {
        int r = tid >> 1, hf = tid & 1;
        float* Srow = S + r * 65 + hf * 32;
        float lmax = -1e30f;
        #pragma unroll
        for (int j = 0; j < 32; j++) lmax = fmaxf(lmax, Srow[j]);
        lmax = fmaxf(lmax, __shfl_xor_sync(0xffffffffu, lmax, 1));
        float lsum = 0.f;
        #pragma unroll
        for (int j = 0; j < 32; j++) {
            float e = expf(Srow[j] - lmax);
            Srow[j] = e;
            lsum += e;
        }
        lsum += __shfl_xor_sync(0xffffffffu, lsum, 1);
        float inv = 1.0f / lsum;
        __half* Prow = Ps + r * PP + hf * 32;
        #pragma unroll
        for (int j = 0; j < 16; j++) {
            __half2 p = __floats2half2_rn(Srow[j * 2] * inv, Srow[j * 2 + 1] * inv);
            *(uint32_t*)&Prow[j * 2] = *(uint32_t*)&p;
        }
    }
    __syncthreads();

    // ---- ctx = P @ V : warp computes rows m0..m0+15 x 128, two 64-col halves ----
    {
        uint32_t pbase = smem_u32(Ps) +
            ((m0 + (lane & 7) + ((lane >> 3) & 1) * 8) * PP + ((lane >> 4) & 1) * 8) * 2;
        uint32_t vbase = smem_u32(Vs) + ((lane & 15) * VP) * 2;
        #pragma unroll
        for (int dh = 0; dh < 2; dh++) {
            float c[8][4];
            #pragma unroll
            for (int j = 0; j < 8; j++)
                #pragma unroll
                for (int q = 0; q < 4; q++) c[j][q] = 0.f;
            #pragma unroll
            for (int ks = 0; ks < 4; ks++) {
                uint32_t a0, a1, a2, a3;
                ldsm_x4(a0, a1, a2, a3, pbase + ks * 32);
                #pragma unroll
                for (int j = 0; j < 8; j++) {
                    int d0 = dh * 64 + j * 8;
                    uint32_t b0, b1;
                    ldsm_x2t(b0, b1, vbase + (ks * 16 * VP + d0) * 2);
                    mma16816(c[j], a0, a1, a2, a3, b0, b1);
                }
            }
            #pragma unroll
            for (int j = 0; j < 8; j++) {
                int d0 = dh * 64 + j * 8 + tig * 2;
                size_t base0 = ((size_t)(b * T_ + m0 + gid))     * D_ + h * HD_ + d0;
                size_t base1 = ((size_t)(b * T_ + m0 + gid + 8)) * D_ + h * HD_ + d0;
                __half2 lo = __floats2half2_rn(c[j][0], c[j][1]);
                __half2 hi = __floats2half2_rn(c[j][2], c[j][3]);
                *(uint32_t*)&g_ctxh[base0] = *(uint32_t*)&lo;
                *(uint32_t*)&g_ctxh[base1] = *(uint32_t*)&hi;
            }
        }
    }
}

// ---------------- residual + LayerNorm ----------------
__global__ void ln_kernel(const float* __restrict__ zinit, const float* __restrict__ gamma,
                          const float* __restrict__ beta, float* __restrict__ out) {
    int row = blockIdx.x;
    int b = row >> 6;
    int tid = threadIdx.x;
    const float* ao = g_atto;
    float x[4];
    float s = 0.f, ss = 0.f;
    #pragma unroll
    for (int q = 0; q < 4; q++) {
        int d = tid + q * 128;
        float zs  = g_zstack[(size_t)row * D_ + d];
        float zdc = zs - 0.05f * (g_zmean[(size_t)b * D_ + d] - zinit[(size_t)b * D_ + d]);
        float v = zdc + ao[(size_t)row * D_ + d];
        x[q] = v; s += v; ss += v * v;
    }
    __shared__ float rs[4], rss[4];
    for (int o = 16; o; o >>= 1) {
        s  += __shfl_down_sync(0xffffffffu, s,  o);
        ss += __shfl_down_sync(0xffffffffu, ss, o);
    }
    if ((tid & 31) == 0) { rs[tid >> 5] = s; rss[tid >> 5] = ss; }
    __syncthreads();
    float sum   = rs[0] + rs[1] + rs[2] + rs[3];
    float sumsq = rss[0] + rss[1] + rss[2] + rss[3];
    float mean = sum * (1.0f / D_);
    float var  = sumsq * (1.0f / D_) - mean * mean;
    float inv  = rsqrtf(var + 1e-5f);
    #pragma unroll
    for (int q = 0; q < 4; q++) {
        int d = tid + q * 128;
        float o = (x[q] - mean) * inv * gamma[d] + beta[d];
        if (isnan(o)) o = 0.f;
        out[(size_t)row * D_ + d] = o;
    }
}

// ---------------- host orchestration ----------------
extern "C" void kernel_launch(void* const* d_in, const int* in_sizes, int n_in,
                              void* d_out, int out_size)
{
    const float* z_init = (const float*)d_in[0];
    const float* tsteps = (const float*)d_in[1];
    const float* W1     = (const float*)d_in[2];
    const float* b1     = (const float*)d_in[3];
    const float* W2     = (const float*)d_in[4];
    const float* b2     = (const float*)d_in[5];
    const float* W3     = (const float*)d_in[6];
    const float* b3     = (const float*)d_in[7];
    const float* Wqkv   = (const float*)d_in[8];
    const float* bqkv   = (const float*)d_in[9];
    const float* Wo     = (const float*)d_in[10];
    const float* bo     = (const float*)d_in[11];
    const float* gamma  = (const float*)d_in[12];
    const float* beta   = (const float*)d_in[13];

    float *zstack, *zmean, *atto;
    __half *w1p, *w2p, *w3p, *wqkvf, *wof, *ctxh, *qkvh;
    cudaGetSymbolAddress((void**)&zstack, g_zstack);
    cudaGetSymbolAddress((void**)&zmean,  g_zmean);
    cudaGetSymbolAddress((void**)&atto,   g_atto);
    cudaGetSymbolAddress((void**)&qkvh,   g_qkvh);
    cudaGetSymbolAddress((void**)&w1p,    g_W1p);
    cudaGetSymbolAddress((void**)&w2p,    g_W2p);
    cudaGetSymbolAddress((void**)&w3p,    g_W3p);
    cudaGetSymbolAddress((void**)&wqkvf,  g_Wqkvf);
    cudaGetSymbolAddress((void**)&wof,    g_Wof);
    cudaGetSymbolAddress((void**)&ctxh,   g_ctxh);

    cudaFuncSetAttribute(attn_kernel, cudaFuncAttributeMaxDynamicSharedMemorySize,
                         ATTN_SMEM_BYTES);
    cudaFuncSetAttribute(ode_kernel, cudaFuncAttributeMaxDynamicSharedMemorySize,
                         SMEM_ODE);
    cudaFuncSetAttribute(hgemm<3*D_, 1, __half>, cudaFuncAttributeMaxDynamicSharedMemorySize,
                         SMEM_HG);
    cudaFuncSetAttribute(hgemm<D_, 0, float>, cudaFuncAttributeMaxDynamicSharedMemorySize,
                         SMEM_HG);

    // 0) pack weights
    pack_w<<<(HID_ * D_) / 256, 256>>>(W1, w1p, HID_ / 16, D_);
    pack_w<<<(HID_ * HID_) / 256, 256>>>(W2, w2p, HID_ / 16, HID_);
    pack_w<<<(D_ * HID_) / 256, 256>>>(W3, w3p, D_ / 16, HID_);
    pack_wb2<<<(4 * D_ * D_) / 256, 256>>>(Wqkv, Wo);

    // 1) fused scale + full RK4 trajectory + zmean (128 CTAs)
    ode_kernel<<<B_ / MB, 512, SMEM_ODE>>>(z_init, tsteps, b1, b2, b3);

    // 2) QKV projection (fused z_dc prep, fp16 output)
    hgemm<3*D_, 1, __half><<<BT_ / 128, 256, SMEM_HG>>>(
        nullptr, zstack, zmean, z_init, wqkvf, bqkv, qkvh);

    // 3) tensor-core attention per (b,h)
    attn_kernel<<<B_ * NH_, 128, ATTN_SMEM_BYTES>>>();

    // 4) output projection (att_out fp32)
    hgemm<D_, 0, float><<<BT_ / 128, 256, SMEM_HG>>>(
        ctxh, nullptr, nullptr, nullptr, wof, bo, atto);

    // 5) residual + LayerNorm
    ln_kernel<<<BT_, 128>>>(z_init, gamma, beta, (float*)d_out);
}

// round 16
// speedup vs baseline: 1.4664x; 1.0200x over previous
#include <cuda_runtime.h>
#include <cuda_fp16.h>
#include <stdint.h>
#include <math.h>

#define B_   1024
#define T_   64
#define D_   512
#define HID_ 256
#define NH_  4
#define HD_  128
#define BT_  (B_*T_)

// ---------------- scratch ----------------
__device__ float  g_zstack[(size_t)BT_*D_];   // [B,T,D] trajectory (fp32)
__device__ float  g_zmean[B_*D_];             // mean over T
__device__ __half g_qkvh[(size_t)BT_*3*D_];   // qkv fp16
__device__ float  g_atto[(size_t)BT_*D_];     // att_out fp32
__device__ __half g_ctxh[(size_t)BT_*D_];     // attention context fp16
// packed fp16 fragment-major weights
__device__ __half g_W1p[HID_*D_];
__device__ __half g_W2p[HID_*HID_];
__device__ __half g_W3p[D_*HID_];
__device__ __half g_Wqkvf[3*D_*D_];
__device__ __half g_Wof[D_*D_];

// ---------------- helpers ----------------
__device__ __forceinline__ float gelu_f(float x) {
    return 0.5f * x * (1.0f + erff(x * 0.70710678118654752f));
}

__device__ __forceinline__ void mma16816(float* c, uint32_t a0, uint32_t a1,
                                         uint32_t a2, uint32_t a3,
                                         uint32_t b0, uint32_t b1) {
    asm volatile(
        "mma.sync.aligned.m16n8k16.row.col.f32.f16.f16.f32 "
        "{%0,%1,%2,%3}, {%4,%5,%6,%7}, {%8,%9}, {%0,%1,%2,%3};\n"
        : "+f"(c[0]), "+f"(c[1]), "+f"(c[2]), "+f"(c[3])
        : "r"(a0), "r"(a1), "r"(a2), "r"(a3), "r"(b0), "r"(b1));
}

__device__ __forceinline__ void ldsm_x4(uint32_t& a0, uint32_t& a1, uint32_t& a2,
                                        uint32_t& a3, uint32_t saddr) {
    asm volatile("ldmatrix.sync.aligned.m8n8.x4.shared.b16 {%0,%1,%2,%3}, [%4];\n"
                 : "=r"(a0), "=r"(a1), "=r"(a2), "=r"(a3) : "r"(saddr));
}

__device__ __forceinline__ void ldsm_x2(uint32_t& b0, uint32_t& b1, uint32_t saddr) {
    asm volatile("ldmatrix.sync.aligned.m8n8.x2.shared.b16 {%0,%1}, [%2];\n"
                 : "=r"(b0), "=r"(b1) : "r"(saddr));
}

__device__ __forceinline__ void ldsm_x2t(uint32_t& b0, uint32_t& b1, uint32_t saddr) {
    asm volatile("ldmatrix.sync.aligned.m8n8.x2.trans.shared.b16 {%0,%1}, [%2];\n"
                 : "=r"(b0), "=r"(b1) : "r"(saddr));
}

__device__ __forceinline__ uint32_t smem_u32(const void* p) {
    uint32_t a;
    asm("{ .reg .u64 t; cvta.to.shared.u64 t, %1; cvt.u32.u64 %0, t; }"
        : "=r"(a) : "l"(p));
    return a;
}

// L2-only (no L1 allocation) vector load — intrinsic (compiler-schedulable)
__device__ __forceinline__ uint4 ldcg4(const uint4* p) {
    return __ldcg(p);
}

// ---------------- weight packing (A-operand fragment-major, for ODE) ----------------
__global__ void pack_w(const float* __restrict__ W, __half* __restrict__ out, int nM, int K) {
    int idx = blockIdx.x * 256 + threadIdx.x;
    int j    = idx & 7;
    int lane = (idx >> 3) & 31;
    int tile = idx >> 8;
    int mt = tile % nM;
    int ks = tile / nM;
    int gid = lane >> 2, tig = lane & 3;
    int rr = gid + ((j >> 1) & 1) * 8;
    int cc = tig * 2 + (j & 1) + ((j >> 2) & 1) * 8;
    out[idx] = __float2half_rn(W[(size_t)(mt * 16 + rr) * K + ks * 16 + cc]);
}

// ---------------- weight packing (B-operand fragment-major, for hgemm) ----------------
__device__ __forceinline__ void pack_wb_one(const float* W, __half* out, int idx, int N, int K) {
    int h    = idx & 3;
    int lane = (idx >> 2) & 31;
    int rest = idx >> 7;
    int NKS = K / 16;
    int ks = rest % NKS;
    int nt = rest / NKS;
    int n = nt * 8 + (lane >> 2);
    int k = ks * 16 + (lane & 3) * 2 + (h & 1) + ((h >> 1) << 3);
    out[idx] = __float2half_rn(W[(size_t)n * K + k]);
}

__global__ void pack_wb2(const float* __restrict__ Wqkv, const float* __restrict__ Wo) {
    int idx = blockIdx.x * 256 + threadIdx.x;
    if (idx < 3 * D_ * D_) {
        pack_wb_one(Wqkv, g_Wqkvf, idx, 3 * D_, D_);
    } else {
        pack_wb_one(Wo, g_Wof, idx - 3 * D_ * D_, D_, D_);
    }
}

// ---------------- fused persistent ODE kernel (MB=8, 128 CTAs, 512 threads) ----------------
#define MB  8
#define ZP  516
#define ZBP 520
#define HP  264
#define SMEM_ODE (2*MB*ZP*4 + MB*ZBP*2 + 2*MB*HP*2)   // 49792

template<int NM, int NK, bool GELU, bool CG>
__device__ __forceinline__ void gemm_act(
    const __half* __restrict__ Wp, const float* __restrict__ bias,
    const __half* __restrict__ act, int ap,
    __half* __restrict__ out, int op, int warp, int lane)
{
    int gid = lane >> 2, tig = lane & 3;
    #pragma unroll
    for (int mt = warp; mt < NM; mt += 16) {
        float c0[4] = {0.f,0.f,0.f,0.f};
        const uint4* wp = (const uint4*)Wp + mt * 32 + lane;
        const __half* a0p = act + gid * ap + tig * 2;
        #pragma unroll 8
        for (int ks = 0; ks < NK; ks++) {
            uint4 a = CG ? ldcg4(wp + (size_t)ks * NM * 32)
                         : wp[(size_t)ks * NM * 32];
            uint32_t b00 = *(const uint32_t*)(a0p + ks * 16);
            uint32_t b01 = *(const uint32_t*)(a0p + ks * 16 + 8);
            mma16816(c0, a.x, a.y, a.z, a.w, b00, b01);
        }
        int h0 = mt * 16 + gid;
        float bs0 = __ldg(bias + h0);
        float bs1 = __ldg(bias + h0 + 8);
        int r = tig * 2;
        float v;
        v = c0[0] + bs0; if (GELU) v = gelu_f(v); out[(r + 0) * op + h0    ] = __float2half_rn(v);
        v = c0[1] + bs0; if (GELU) v = gelu_f(v); out[(r + 1) * op + h0    ] = __float2half_rn(v);
        v = c0[2] + bs1; if (GELU) v = gelu_f(v); out[(r + 0) * op + h0 + 8] = __float2half_rn(v);
        v = c0[3] + bs1; if (GELU) v = gelu_f(v); out[(r + 1) * op + h0 + 8] = __float2half_rn(v);
    }
}

__device__ __forceinline__ void gemm3_stage(
    const __half* __restrict__ Wp, const float* __restrict__ b3,
    const __half* __restrict__ act,
    float* Z, float* Zacc, __half* Zbf,
    float wcoef, float ccoef, bool doStage, int warp, int lane)
{
    constexpr int NM = 32, NK = 16;
    int gid = lane >> 2, tig = lane & 3;
    float c0[4] = {0.f,0.f,0.f,0.f}, c1[4] = {0.f,0.f,0.f,0.f};
    const uint4* wp0 = (const uint4*)Wp + warp * 32 + lane;
    const uint4* wp1 = wp0 + 16 * 32;
    const __half* a0p = act + gid * HP + tig * 2;
    #pragma unroll 8
    for (int ks = 0; ks < NK; ks++) {
        uint4 a0 = ldcg4(wp0 + (size_t)ks * NM * 32);
        uint4 a1 = ldcg4(wp1 + (size_t)ks * NM * 32);
        uint32_t b00 = *(const uint32_t*)(a0p + ks * 16);
        uint32_t b01 = *(const uint32_t*)(a0p + ks * 16 + 8);
        mma16816(c0, a0.x, a0.y, a0.z, a0.w, b00, b01);
        mma16816(c1, a1.x, a1.y, a1.z, a1.w, b00, b01);
    }
    #pragma unroll
    for (int m = 0; m < 2; m++) {
        const float* cm = m ? c1 : c0;
        int d0 = (warp + m * 16) * 16 + gid;
        float bv0 = __ldg(b3 + d0);
        float bv1 = __ldg(b3 + d0 + 8);
        int r = tig * 2;
        float k;
        #define ODE_DO(cc_, dd_, rr_, bb_)                                          \
            { k = (cc_) + (bb_);                                                    \
              Zacc[(rr_) * ZP + (dd_)] += wcoef * k;                                \
              if (doStage) Zbf[(rr_) * ZBP + (dd_)] =                               \
                  __float2half_rn(Z[(rr_) * ZP + (dd_)] + ccoef * k); }
        ODE_DO(cm[0], d0,     r,     bv0)
        ODE_DO(cm[1], d0,     r + 1, bv0)
        ODE_DO(cm[2], d0 + 8, r,     bv1)
        ODE_DO(cm[3], d0 + 8, r + 1, bv1)
        #undef ODE_DO
    }
}

__global__ void __launch_bounds__(512, 1) ode_kernel(
    const float* __restrict__ zinit, const float* __restrict__ tsteps,
    const float* __restrict__ b1, const float* __restrict__ b2,
    const float* __restrict__ b3)
{
    extern __shared__ char smchar[];
    float*  Z    = (float*)(smchar);
    float*  Zacc = (float*)(smchar + MB * ZP * 4);
    __half* Zbf  = (__half*)(smchar + 2 * MB * ZP * 4);
    __half* H1   = (__half*)(smchar + 2 * MB * ZP * 4 + MB * ZBP * 2);
    __half* H2   = H1 + MB * HP;

    int tid = threadIdx.x, warp = tid >> 5, lane = tid & 31;
    int r0 = blockIdx.x * MB;
    float dt = __ldg(tsteps + 1) - __ldg(tsteps);

    // ---- input-adaptive scale (one warp per row, warps 0-7) ----
    if (warp < MB) {
        int r = warp;
        int sub = lane;
        const float* zr = zinit + (size_t)(r0 + r) * D_;
        float vals[16];
        float s = 0.f, ss = 0.f;
        #pragma unroll
        for (int i = 0; i < 16; i++) {
            float v = zr[sub + i * 32];
            vals[i] = v; s += v; ss += v * v;
        }
        for (int o = 16; o; o >>= 1) {
            s  += __shfl_down_sync(0xffffffffu, s,  o);
            ss += __shfl_down_sync(0xffffffffu, ss, o);
        }
        s  = __shfl_sync(0xffffffffu, s,  0);
        ss = __shfl_sync(0xffffffffu, ss, 0);
        float mean = s * (1.f / D_);
        float var  = (ss - s * mean) * (1.f / (D_ - 1));
        float sc   = sqrtf(ss) / (var + 1e-6f);
        sc = fminf(fmaxf(sc, 0.8f), 1.2f);
        #pragma unroll
        for (int i = 0; i < 16; i++) {
            float z = vals[i] * sc;
            int d = sub + i * 32;
            Z[r * ZP + d] = z;
            Zacc[r * ZP + d] = z;
            Zbf[r * ZBP + d] = __float2half_rn(z);
        }
    }
    __syncthreads();

    const float wc[4] = {1.f, 2.f, 2.f, 1.f};
    const float cc[4] = {0.5f, 0.5f, 1.f, 0.f};

    float zsum[MB];
    #pragma unroll
    for (int j = 0; j < MB; j++) zsum[j] = 0.f;

    for (int t = 0; t < T_; t++) {
        #pragma unroll 1
        for (int e = 0; e < 4; e++) {
            gemm_act<16, 32, true, true >(g_W1p, b1, Zbf, ZBP, H1, HP, warp, lane);
            __syncthreads();
            gemm_act<16, 16, true, false>(g_W2p, b2, H1, HP, H2, HP, warp, lane);
            __syncthreads();
            gemm3_stage(g_W3p, b3, H2, Z, Zacc, Zbf,
                        dt * (1.f / 6.f) * wc[e], dt * cc[e], e < 3, warp, lane);
            __syncthreads();
        }
        #pragma unroll
        for (int j = 0; j < MB; j++) {
            int i = tid + j * 512;
            int r = i >> 9, d = i & 511;
            float z = Zacc[r * ZP + d];
            if (isnan(z)) z = 0.f;
            Z[r * ZP + d] = z;
            Zacc[r * ZP + d] = z;
            Zbf[r * ZBP + d] = __float2half_rn(z);
            zsum[j] += z;
            g_zstack[((size_t)(r0 + r) * T_ + t) * D_ + d] = z;
        }
        __syncthreads();
    }

    // ---- write zmean (fused; same t-ascending summation order) ----
    #pragma unroll
    for (int j = 0; j < MB; j++) {
        int i = tid + j * 512;
        int r = i >> 9, d = i & 511;
        g_zmean[(size_t)(r0 + r) * D_ + d] = zsum[j] * (1.0f / T_);
    }
}

// ---------------- hgemm + optional fused z_dc A-prep ----------------
#define AP 520
#define SMEM_HG (128*AP*2)

template<int NTOT, int MODE, typename OT>
__global__ void __launch_bounds__(256, 1) hgemm(
    const __half* __restrict__ Act,
    const float* __restrict__ zstack, const float* __restrict__ zmean,
    const float* __restrict__ zinit,
    const __half* __restrict__ Wf,
    const float* __restrict__ bias, OT* __restrict__ C)
{
    extern __shared__ __half As[];
    int tid = threadIdx.x, warp = tid >> 5, lane = tid & 31;
    int m0 = blockIdx.x * 128;

    if (MODE == 0) {
        for (int i = tid; i < 128 * 64; i += 256) {
            int r = i >> 6, c = i & 63;
            *(uint4*)&As[r * AP + c * 8] =
                *(const uint4*)&Act[(size_t)(m0 + r) * 512 + c * 8];
        }
    } else {
        for (int i = tid; i < 128 * 128; i += 256) {
            int r = i >> 7, c = (i & 127) * 4;
            int row = m0 + r;
            int b = row >> 6;
            float4 zs = *(const float4*)&zstack[(size_t)row * 512 + c];
            float4 zm = *(const float4*)&zmean[(size_t)b * 512 + c];
            float4 zi = *(const float4*)&zinit[(size_t)b * 512 + c];
            __half2 h01 = __floats2half2_rn(zs.x - 0.05f * (zm.x - zi.x),
                                            zs.y - 0.05f * (zm.y - zi.y));
            __half2 h23 = __floats2half2_rn(zs.z - 0.05f * (zm.z - zi.z),
                                            zs.w - 0.05f * (zm.w - zi.w));
            uint2 u;
            u.x = *(uint32_t*)&h01; u.y = *(uint32_t*)&h23;
            *(uint2*)&As[r * AP + c] = u;
        }
    }
    __syncthreads();

    int mw = warp * 16;
    int arow = mw + (lane & 7) + ((lane >> 3) & 1) * 8;
    int acol = ((lane >> 4) & 1) * 8;
    uint32_t abase = smem_u32(As) + (arow * AP + acol) * 2;

    int r = lane >> 2, cpair = (lane & 3) * 2;

    for (int ng = 0; ng < NTOT / 64; ng++) {
        float acc[8][4];
        #pragma unroll
        for (int j = 0; j < 8; j++)
            #pragma unroll
            for (int q = 0; q < 4; q++) acc[j][q] = 0.f;

        const uint2* wbase = (const uint2*)Wf + ((size_t)ng * 8 * 32) * 32 + lane;
        #pragma unroll 4
        for (int ks = 0; ks < 32; ks++) {
            uint32_t a0, a1, a2, a3;
            ldsm_x4(a0, a1, a2, a3, abase + ks * 32);
            #pragma unroll
            for (int j = 0; j < 8; j++) {
                uint2 b = wbase[((size_t)j * 32 + ks) * 32];
                mma16816(acc[j], a0, a1, a2, a3, b.x, b.y);
            }
        }
        #pragma unroll
        for (int j = 0; j < 8; j++) {
            int n = ng * 64 + j * 8 + cpair;
            float bv0 = __ldg(bias + n), bv1 = __ldg(bias + n + 1);
            float v00 = acc[j][0] + bv0, v01 = acc[j][1] + bv1;
            float v10 = acc[j][2] + bv0, v11 = acc[j][3] + bv1;
            if (sizeof(OT) == 2) {
                __half2 lo = __floats2half2_rn(v00, v01);
                __half2 hi = __floats2half2_rn(v10, v11);
                *(uint32_t*)&C[(size_t)(m0 + mw + r)     * NTOT + n] = *(uint32_t*)&lo;
                *(uint32_t*)&C[(size_t)(m0 + mw + r + 8) * NTOT + n] = *(uint32_t*)&hi;
            } else {
                *(float2*)&C[(size_t)(m0 + mw + r)     * NTOT + n] = make_float2(v00, v01);
                *(float2*)&C[(size_t)(m0 + mw + r + 8) * NTOT + n] = make_float2(v10, v11);
            }
        }
    }
}

// ---------------- tensor-core attention: per (b,h), 128 threads ----------------
// Register-resident softmax: each warp owns its 16 score rows entirely, so
// softmax reduces over the tig-quad (shfl_xor 1,2) and the softmaxed P tiles
// are repacked directly into m16n8k16 A-fragments — no S/P smem round-trip,
// no ldmatrix for P, only one barrier (after the QKV load).
#define VP 136                               // Q/K/V fp16 pitch
#define ATTN_SMEM_BYTES (3*64*VP*2)          // 52224

__global__ void __launch_bounds__(128) attn_kernel() {
    extern __shared__ char sm[];
    __half* Qs = (__half*)(sm);
    __half* Ks = (__half*)(sm + 64 * VP * 2);
    __half* Vs = (__half*)(sm + 2 * 64 * VP * 2);

    int tid = threadIdx.x, warp = tid >> 5, lane = tid & 31;
    int bh = blockIdx.x;
    int b = bh >> 2, h = bh & 3;
    int gid = lane >> 2, tig = lane & 3;

    // ---- load Q,K,V fp16 directly ----
    for (int idx = tid; idx < 64 * 16; idx += 128) {
        int t = idx >> 4, c = (idx & 15) * 8;
        size_t base = ((size_t)(b * T_ + t)) * (3 * D_) + h * HD_ + c;
        #pragma unroll
        for (int w = 0; w < 3; w++) {
            *(uint4*)&((__half*)(sm + w * 64 * VP * 2))[t * VP + c] =
                *(const uint4*)&g_qkvh[base + (size_t)w * D_];
        }
    }
    __syncthreads();

    int m0 = warp * 16;

    // ---- scores: warp computes rows [m0, m0+16) x 64 into registers ----
    float c[8][4];
    {
        uint32_t qbase = smem_u32(Qs) +
            ((m0 + (lane & 7) + ((lane >> 3) & 1) * 8) * VP + ((lane >> 4) & 1) * 8) * 2;
        uint32_t kbase = smem_u32(Ks) +
            (((lane & 15) & 7) * VP + (((lane & 15) >> 3)) * 8) * 2;
        #pragma unroll
        for (int j = 0; j < 8; j++)
            #pragma unroll
            for (int q = 0; q < 4; q++) c[j][q] = 0.f;
        #pragma unroll
        for (int ks = 0; ks < 8; ks++) {
            uint32_t a0, a1, a2, a3;
            ldsm_x4(a0, a1, a2, a3, qbase + ks * 32);
            #pragma unroll
            for (int j = 0; j < 8; j++) {
                uint32_t b0, b1;
                ldsm_x2(b0, b1, kbase + (j * 8 * VP + ks * 16) * 2);
                mma16816(c[j], a0, a1, a2, a3, b0, b1);
            }
        }
    }

    // ---- softmax in registers (rows gid and gid+8 of this warp's tile) ----
    uint32_t pa[4][4];   // A-fragments for PV: pa[ks] = {a0,a1,a2,a3}
    {
        const float sc = 0.08838834764831845f;   // 1/sqrt(128)
        float mx0 = -1e30f, mx1 = -1e30f;
        #pragma unroll
        for (int j = 0; j < 8; j++) {
            c[j][0] *= sc; c[j][1] *= sc; c[j][2] *= sc; c[j][3] *= sc;
            mx0 = fmaxf(mx0, fmaxf(c[j][0], c[j][1]));
            mx1 = fmaxf(mx1, fmaxf(c[j][2], c[j][3]));
        }
        mx0 = fmaxf(mx0, __shfl_xor_sync(0xffffffffu, mx0, 1));
        mx0 = fmaxf(mx0, __shfl_xor_sync(0xffffffffu, mx0, 2));
        mx1 = fmaxf(mx1, __shfl_xor_sync(0xffffffffu, mx1, 1));
        mx1 = fmaxf(mx1, __shfl_xor_sync(0xffffffffu, mx1, 2));
        float s0 = 0.f, s1 = 0.f;
        #pragma unroll
        for (int j = 0; j < 8; j++) {
            c[j][0] = expf(c[j][0] - mx0); s0 += c[j][0];
            c[j][1] = expf(c[j][1] - mx0); s0 += c[j][1];
            c[j][2] = expf(c[j][2] - mx1); s1 += c[j][2];
            c[j][3] = expf(c[j][3] - mx1); s1 += c[j][3];
        }
        s0 += __shfl_xor_sync(0xffffffffu, s0, 1);
        s0 += __shfl_xor_sync(0xffffffffu, s0, 2);
        s1 += __shfl_xor_sync(0xffffffffu, s1, 1);
        s1 += __shfl_xor_sync(0xffffffffu, s1, 2);
        float inv0 = 1.0f / s0, inv1 = 1.0f / s1;
        #pragma unroll
        for (int ks = 0; ks < 4; ks++) {
            // k-chunk ks covers score cols ks*16 .. ks*16+15 -> j = 2ks (k-lo), 2ks+1 (k-hi)
            __half2 h00 = __floats2half2_rn(c[2*ks    ][0] * inv0, c[2*ks    ][1] * inv0);
            __half2 h10 = __floats2half2_rn(c[2*ks    ][2] * inv1, c[2*ks    ][3] * inv1);
            __half2 h01 = __floats2half2_rn(c[2*ks + 1][0] * inv0, c[2*ks + 1][1] * inv0);
            __half2 h11 = __floats2half2_rn(c[2*ks + 1][2] * inv1, c[2*ks + 1][3] * inv1);
            pa[ks][0] = *(uint32_t*)&h00;   // row gid,   k-lo
            pa[ks][1] = *(uint32_t*)&h10;   // row gid+8, k-lo
            pa[ks][2] = *(uint32_t*)&h01;   // row gid,   k-hi
            pa[ks][3] = *(uint32_t*)&h11;   // row gid+8, k-hi
        }
    }

    // ---- ctx = P @ V : two 64-col halves, P fragments from registers ----
    {
        uint32_t vbase = smem_u32(Vs) + ((lane & 15) * VP) * 2;
        #pragma unroll
        for (int dh = 0; dh < 2; dh++) {
            float o[8][4];
            #pragma unroll
            for (int j = 0; j < 8; j++)
                #pragma unroll
                for (int q = 0; q < 4; q++) o[j][q] = 0.f;
            #pragma unroll
            for (int ks = 0; ks < 4; ks++) {
                #pragma unroll
                for (int j = 0; j < 8; j++) {
                    int d0 = dh * 64 + j * 8;
                    uint32_t b0, b1;
                    ldsm_x2t(b0, b1, vbase + (ks * 16 * VP + d0) * 2);
                    mma16816(o[j], pa[ks][0], pa[ks][1], pa[ks][2], pa[ks][3], b0, b1);
                }
            }
            #pragma unroll
            for (int j = 0; j < 8; j++) {
                int d0 = dh * 64 + j * 8 + tig * 2;
                size_t base0 = ((size_t)(b * T_ + m0 + gid))     * D_ + h * HD_ + d0;
                size_t base1 = ((size_t)(b * T_ + m0 + gid + 8)) * D_ + h * HD_ + d0;
                __half2 lo = __floats2half2_rn(o[j][0], o[j][1]);
                __half2 hi = __floats2half2_rn(o[j][2], o[j][3]);
                *(uint32_t*)&g_ctxh[base0] = *(uint32_t*)&lo;
                *(uint32_t*)&g_ctxh[base1] = *(uint32_t*)&hi;
            }
        }
    }
}

// ---------------- residual + LayerNorm ----------------
__global__ void ln_kernel(const float* __restrict__ zinit, const float* __restrict__ gamma,
                          const float* __restrict__ beta, float* __restrict__ out) {
    int row = blockIdx.x;
    int b = row >> 6;
    int tid = threadIdx.x;
    const float* ao = g_atto;
    float x[4];
    float s = 0.f, ss = 0.f;
    #pragma unroll
    for (int q = 0; q < 4; q++) {
        int d = tid + q * 128;
        float zs  = g_zstack[(size_t)row * D_ + d];
        float zdc = zs - 0.05f * (g_zmean[(size_t)b * D_ + d] - zinit[(size_t)b * D_ + d]);
        float v = zdc + ao[(size_t)row * D_ + d];
        x[q] = v; s += v; ss += v * v;
    }
    __shared__ float rs[4], rss[4];
    for (int o = 16; o; o >>= 1) {
        s  += __shfl_down_sync(0xffffffffu, s,  o);
        ss += __shfl_down_sync(0xffffffffu, ss, o);
    }
    if ((tid & 31) == 0) { rs[tid >> 5] = s; rss[tid >> 5] = ss; }
    __syncthreads();
    float sum   = rs[0] + rs[1] + rs[2] + rs[3];
    float sumsq = rss[0] + rss[1] + rss[2] + rss[3];
    float mean = sum * (1.0f / D_);
    float var  = sumsq * (1.0f / D_) - mean * mean;
    float inv  = rsqrtf(var + 1e-5f);
    #pragma unroll
    for (int q = 0; q < 4; q++) {
        int d = tid + q * 128;
        float o = (x[q] - mean) * inv * gamma[d] + beta[d];
        if (isnan(o)) o = 0.f;
        out[(size_t)row * D_ + d] = o;
    }
}

// ---------------- host orchestration ----------------
extern "C" void kernel_launch(void* const* d_in, const int* in_sizes, int n_in,
                              void* d_out, int out_size)
{
    const float* z_init = (const float*)d_in[0];
    const float* tsteps = (const float*)d_in[1];
    const float* W1     = (const float*)d_in[2];
    const float* b1     = (const float*)d_in[3];
    const float* W2     = (const float*)d_in[4];
    const float* b2     = (const float*)d_in[5];
    const float* W3     = (const float*)d_in[6];
    const float* b3     = (const float*)d_in[7];
    const float* Wqkv   = (const float*)d_in[8];
    const float* bqkv   = (const float*)d_in[9];
    const float* Wo     = (const float*)d_in[10];
    const float* bo     = (const float*)d_in[11];
    const float* gamma  = (const float*)d_in[12];
    const float* beta   = (const float*)d_in[13];

    float *zstack, *zmean, *atto;
    __half *w1p, *w2p, *w3p, *wqkvf, *wof, *ctxh, *qkvh;
    cudaGetSymbolAddress((void**)&zstack, g_zstack);
    cudaGetSymbolAddress((void**)&zmean,  g_zmean);
    cudaGetSymbolAddress((void**)&atto,   g_atto);
    cudaGetSymbolAddress((void**)&qkvh,   g_qkvh);
    cudaGetSymbolAddress((void**)&w1p,    g_W1p);
    cudaGetSymbolAddress((void**)&w2p,    g_W2p);
    cudaGetSymbolAddress((void**)&w3p,    g_W3p);
    cudaGetSymbolAddress((void**)&wqkvf,  g_Wqkvf);
    cudaGetSymbolAddress((void**)&wof,    g_Wof);
    cudaGetSymbolAddress((void**)&ctxh,   g_ctxh);

    cudaFuncSetAttribute(attn_kernel, cudaFuncAttributeMaxDynamicSharedMemorySize,
                         ATTN_SMEM_BYTES);
    cudaFuncSetAttribute(ode_kernel, cudaFuncAttributeMaxDynamicSharedMemorySize,
                         SMEM_ODE);
    cudaFuncSetAttribute(hgemm<3*D_, 1, __half>, cudaFuncAttributeMaxDynamicSharedMemorySize,
                         SMEM_HG);
    cudaFuncSetAttribute(hgemm<D_, 0, float>, cudaFuncAttributeMaxDynamicSharedMemorySize,
                         SMEM_HG);

    // 0) pack weights
    pack_w<<<(HID_ * D_) / 256, 256>>>(W1, w1p, HID_ / 16, D_);
    pack_w<<<(HID_ * HID_) / 256, 256>>>(W2, w2p, HID_ / 16, HID_);
    pack_w<<<(D_ * HID_) / 256, 256>>>(W3, w3p, D_ / 16, HID_);
    pack_wb2<<<(4 * D_ * D_) / 256, 256>>>(Wqkv, Wo);

    // 1) fused scale + full RK4 trajectory + zmean (128 CTAs)
    ode_kernel<<<B_ / MB, 512, SMEM_ODE>>>(z_init, tsteps, b1, b2, b3);

    // 2) QKV projection (fused z_dc prep, fp16 output)
    hgemm<3*D_, 1, __half><<<BT_ / 128, 256, SMEM_HG>>>(
        nullptr, zstack, zmean, z_init, wqkvf, bqkv, qkvh);

    // 3) tensor-core attention per (b,h), register-resident softmax
    attn_kernel<<<B_ * NH_, 128, ATTN_SMEM_BYTES>>>();

    // 4) output projection (att_out fp32)
    hgemm<D_, 0, float><<<BT_ / 128, 256, SMEM_HG>>>(
        ctxh, nullptr, nullptr, nullptr, wof, bo, atto);

    // 5) residual + LayerNorm
    ln_kernel<<<BT_, 128>>>(z_init, gamma, beta, (float*)d_out);
}